// round 7
// baseline (speedup 1.0000x reference)
#include <cuda_runtime.h>
#include <math.h>

#define B_SZ   2
#define NTOK   2048
#define DIM    1024
#define NH     16
#define HD     64
#define M_TOT  (B_SZ * NTOK)      // 4096

// ---------------- scratch (device globals; no runtime allocation) ----------
__device__ float g_q[B_SZ * NH * NTOK * HD];   // [B,H,N,hd]
__device__ float g_k[B_SZ * NH * NTOK * HD];
__device__ float g_v[B_SZ * NH * NTOK * HD];
__device__ float g_h[M_TOT * DIM];             // attention output [B,N,DIM]
__device__ float g_gate[M_TOT];                // per-token gate scalar

// ===========================================================================
// Kernel 1: fused QKV projection.  Y = x @ W^T + b  for Wq/Wk/Wv,
// written directly in [B,H,N,hd] layout.  NT-GEMM, 128x128x16 tiles.
// grid = (M/128, 3072/128) = (32, 24), 256 threads.
// ===========================================================================
__global__ __launch_bounds__(256) void qkv_gemm(
    const float* __restrict__ x,
    const float* __restrict__ Wq, const float* __restrict__ bq,
    const float* __restrict__ Wk, const float* __restrict__ bk,
    const float* __restrict__ Wv, const float* __restrict__ bv)
{
    __shared__ float As[16][128];
    __shared__ float Bs[16][128];

    const int tid = threadIdx.x;
    const int tx = tid & 15, ty = tid >> 4;
    const int m0 = blockIdx.x * 128;
    const int n0 = blockIdx.y * 128;          // 0..3071
    const int seg = n0 >> 10;                 // 0=q 1=k 2=v (128 | 1024)
    const float* W    = (seg == 0) ? Wq : (seg == 1) ? Wk : Wv;
    const float* bias = (seg == 0) ? bq : (seg == 1) ? bk : bv;
    float* outp       = (seg == 0) ? g_q : (seg == 1) ? g_k : g_v;
    const int ncol0 = n0 & 1023;

    const int lr = tid >> 1;                  // 0..127
    const int lk = (tid & 1) * 8;             // 0 or 8

    float acc[8][8];
#pragma unroll
    for (int i = 0; i < 8; i++)
#pragma unroll
        for (int j = 0; j < 8; j++) acc[i][j] = 0.f;

    const float* aPtr = x + (m0 + lr) * DIM + lk;
    const float* bPtr = W + (ncol0 + lr) * DIM + lk;

    for (int k0 = 0; k0 < DIM; k0 += 16) {
#pragma unroll
        for (int h = 0; h < 2; h++) {
            float4 av  = *(const float4*)(aPtr + k0 + h * 4);
            float4 bv4 = *(const float4*)(bPtr + k0 + h * 4);
            As[lk + h * 4 + 0][lr] = av.x;  As[lk + h * 4 + 1][lr] = av.y;
            As[lk + h * 4 + 2][lr] = av.z;  As[lk + h * 4 + 3][lr] = av.w;
            Bs[lk + h * 4 + 0][lr] = bv4.x; Bs[lk + h * 4 + 1][lr] = bv4.y;
            Bs[lk + h * 4 + 2][lr] = bv4.z; Bs[lk + h * 4 + 3][lr] = bv4.w;
        }
        __syncthreads();
#pragma unroll
        for (int kk = 0; kk < 16; kk++) {
            float4 a0 = *(const float4*)&As[kk][8 * ty];
            float4 a1 = *(const float4*)&As[kk][8 * ty + 4];
            float4 b0 = *(const float4*)&Bs[kk][8 * tx];
            float4 b1 = *(const float4*)&Bs[kk][8 * tx + 4];
            float ar[8] = {a0.x, a0.y, a0.z, a0.w, a1.x, a1.y, a1.z, a1.w};
            float br_[8] = {b0.x, b0.y, b0.z, b0.w, b1.x, b1.y, b1.z, b1.w};
#pragma unroll
            for (int i = 0; i < 8; i++)
#pragma unroll
                for (int j = 0; j < 8; j++) acc[i][j] += ar[i] * br_[j];
        }
        __syncthreads();
    }

    // epilogue: bias + scatter to [B,H,N,hd]
#pragma unroll
    for (int i = 0; i < 8; i++) {
        int m = m0 + 8 * ty + i;
        int b = m >> 11, n = m & 2047;
#pragma unroll
        for (int j4 = 0; j4 < 2; j4++) {
            int col = ncol0 + 8 * tx + j4 * 4;   // 0..1023, 4-aligned
            int head = col >> 6, d = col & 63;
            float4 vo;
            vo.x = acc[i][j4 * 4 + 0] + bias[col + 0];
            vo.y = acc[i][j4 * 4 + 1] + bias[col + 1];
            vo.z = acc[i][j4 * 4 + 2] + bias[col + 2];
            vo.w = acc[i][j4 * 4 + 3] + bias[col + 3];
            *(float4*)&outp[(((b * NH + head) * NTOK) + n) * HD + d] = vo;
        }
    }
}

// ===========================================================================
// Kernel 2: flash attention with fused Q preprocessing.
// grid = (N/64 = 32 query tiles, B*H = 32), 256 threads.
// dynamic smem: Qt/Kt/Vs/Pt each [64][68] floats.
// ===========================================================================
#define ATTN_SMEM (4 * 64 * 68 * 4)

__global__ __launch_bounds__(256) void attn_kernel(
    const float* __restrict__ temperature,
    const float* __restrict__ qe)
{
    extern __shared__ float sm[];
    float* Qt = sm;                 // [d][r], stride 68
    float* Kt = Qt + 64 * 68;       // [d][j]
    float* Vs = Kt + 64 * 68;       // [j][d]
    float* Pt = Vs + 64 * 68;       // [j][r]

    const int tid = threadIdx.x;
    const int tx = tid & 15, ty = tid >> 4;
    const int bh = blockIdx.y;
    const int b = bh >> 4, hh = bh & 15;
    const int q0 = blockIdx.x * 64;

    const float* qbase = g_q + (bh * NTOK + q0) * HD;
    const float* kbase = g_k + (long)bh * NTOK * HD;
    const float* vbase = g_v + (long)bh * NTOK * HD;

    // ---- load + preprocess Q: (q/||q|| + qe) * softplus(t)/8, store transposed
    {
        int r  = tid >> 2;
        int c4 = tid & 3;
        float4 v[4];
#pragma unroll
        for (int f = 0; f < 4; f++)
            v[f] = *(const float4*)(qbase + r * HD + c4 * 16 + f * 4);
        float ss = 0.f;
#pragma unroll
        for (int f = 0; f < 4; f++)
            ss += v[f].x * v[f].x + v[f].y * v[f].y + v[f].z * v[f].z + v[f].w * v[f].w;
        ss += __shfl_xor_sync(0xffffffffu, ss, 1);
        ss += __shfl_xor_sync(0xffffffffu, ss, 2);
        float inv = rsqrtf(ss);
        float t  = temperature[hh];
        float sp = (t > 20.f) ? t : log1pf(__expf(t));
        float tc = sp * 0.125f;                       // /sqrt(64)
        const float* qeh = qe + hh * HD;
#pragma unroll
        for (int f = 0; f < 4; f++) {
            int d = c4 * 16 + f * 4;
            Qt[(d + 0) * 68 + r] = (v[f].x * inv + qeh[d + 0]) * tc;
            Qt[(d + 1) * 68 + r] = (v[f].y * inv + qeh[d + 1]) * tc;
            Qt[(d + 2) * 68 + r] = (v[f].z * inv + qeh[d + 2]) * tc;
            Qt[(d + 3) * 68 + r] = (v[f].w * inv + qeh[d + 3]) * tc;
        }
    }
    __syncthreads();

    float o[16];
    float mi[4], li[4];
#pragma unroll
    for (int i = 0; i < 16; i++) o[i] = 0.f;
#pragma unroll
    for (int i = 0; i < 4; i++) { mi[i] = -1e30f; li[i] = 0.f; }

    for (int kt = 0; kt < NTOK / 64; kt++) {
        // ---- load K (transposed) and V tiles
        {
            int j = tid >> 2, c4 = tid & 3;
            const float* kp = kbase + (kt * 64 + j) * HD + c4 * 16;
            const float* vp = vbase + (kt * 64 + j) * HD + c4 * 16;
#pragma unroll
            for (int f = 0; f < 4; f++) {
                float4 kv = *(const float4*)(kp + f * 4);
                int d = c4 * 16 + f * 4;
                Kt[(d + 0) * 68 + j] = kv.x; Kt[(d + 1) * 68 + j] = kv.y;
                Kt[(d + 2) * 68 + j] = kv.z; Kt[(d + 3) * 68 + j] = kv.w;
                float4 vv = *(const float4*)(vp + f * 4);
                *(float4*)&Vs[j * 68 + d] = vv;
            }
        }
        __syncthreads();

        // ---- S = Q K^T  (4x4 microtile per thread)
        float s[16];
#pragma unroll
        for (int i = 0; i < 16; i++) s[i] = 0.f;
#pragma unroll 8
        for (int d = 0; d < 64; d++) {
            float4 qv = *(const float4*)&Qt[d * 68 + 4 * ty];
            float4 kv = *(const float4*)&Kt[d * 68 + 4 * tx];
            float qa[4] = {qv.x, qv.y, qv.z, qv.w};
            float ka[4] = {kv.x, kv.y, kv.z, kv.w};
#pragma unroll
            for (int i = 0; i < 4; i++)
#pragma unroll
                for (int j = 0; j < 4; j++) s[i * 4 + j] += qa[i] * ka[j];
        }

        // ---- online softmax per row (rows owned across the 16-lane half-warp)
#pragma unroll
        for (int i = 0; i < 4; i++) {
            float rm = fmaxf(fmaxf(s[i * 4], s[i * 4 + 1]), fmaxf(s[i * 4 + 2], s[i * 4 + 3]));
            rm = fmaxf(rm, __shfl_xor_sync(0xffffffffu, rm, 1, 16));
            rm = fmaxf(rm, __shfl_xor_sync(0xffffffffu, rm, 2, 16));
            rm = fmaxf(rm, __shfl_xor_sync(0xffffffffu, rm, 4, 16));
            rm = fmaxf(rm, __shfl_xor_sync(0xffffffffu, rm, 8, 16));
            float mnew = fmaxf(mi[i], rm);
            float corr = __expf(mi[i] - mnew);
            float rs = 0.f;
#pragma unroll
            for (int j = 0; j < 4; j++) { s[i * 4 + j] = __expf(s[i * 4 + j] - mnew); rs += s[i * 4 + j]; }
            rs += __shfl_xor_sync(0xffffffffu, rs, 1, 16);
            rs += __shfl_xor_sync(0xffffffffu, rs, 2, 16);
            rs += __shfl_xor_sync(0xffffffffu, rs, 4, 16);
            rs += __shfl_xor_sync(0xffffffffu, rs, 8, 16);
            li[i] = li[i] * corr + rs;
            mi[i] = mnew;
#pragma unroll
            for (int j = 0; j < 4; j++) o[i * 4 + j] *= corr;
#pragma unroll
            for (int j = 0; j < 4; j++)
                Pt[(4 * tx + j) * 68 + 4 * ty + i] = s[i * 4 + j];
        }
        __syncthreads();

        // ---- O += P V
#pragma unroll 8
        for (int jj = 0; jj < 64; jj++) {
            float4 pv = *(const float4*)&Pt[jj * 68 + 4 * ty];
            float4 vv = *(const float4*)&Vs[jj * 68 + 4 * tx];
            float pa[4] = {pv.x, pv.y, pv.z, pv.w};
            float va[4] = {vv.x, vv.y, vv.z, vv.w};
#pragma unroll
            for (int i = 0; i < 4; i++)
#pragma unroll
                for (int j = 0; j < 4; j++) o[i * 4 + j] += pa[i] * va[j];
        }
        __syncthreads();
    }

    // ---- epilogue: normalize and write h in [B,N,DIM] layout
#pragma unroll
    for (int i = 0; i < 4; i++) {
        float invl = 1.0f / li[i];
        int n = q0 + 4 * ty + i;
        float4 vo;
        vo.x = o[i * 4 + 0] * invl; vo.y = o[i * 4 + 1] * invl;
        vo.z = o[i * 4 + 2] * invl; vo.w = o[i * 4 + 3] * invl;
        *(float4*)&g_h[(b * NTOK + n) * DIM + hh * HD + 4 * tx] = vo;
    }
}

// ===========================================================================
// Kernel 3: gating -> scalar g per token.  One warp per token.
// g = 2*s0*(s0+s1) + 6*s1*sum(top3 softmax15)
// grid = 512, 256 threads (8 warps).
// ===========================================================================
__global__ __launch_bounds__(256) void gate_kernel(
    const float* __restrict__ Wr, const float* __restrict__ br,
    const float* __restrict__ Ws, const float* __restrict__ bs)
{
    const int warp = threadIdx.x >> 5, lane = threadIdx.x & 31;
    const int tok = blockIdx.x * 8 + warp;
    const float* hrow = g_h + tok * DIM;

    float hv[32];
#pragma unroll
    for (int kk = 0; kk < 32; kk++) hv[kk] = hrow[lane + 32 * kk];

    float myLogit = -1e30f;
#pragma unroll
    for (int wi = 0; wi < 17; wi++) {
        const float* wrow = (wi < 15) ? (Wr + wi * DIM) : (Ws + (wi - 15) * DIM);
        float sum = 0.f;
#pragma unroll
        for (int kk = 0; kk < 32; kk++) sum += hv[kk] * wrow[lane + 32 * kk];
#pragma unroll
        for (int off = 16; off; off >>= 1) sum += __shfl_xor_sync(0xffffffffu, sum, off);
        float bias = (wi < 15) ? br[wi] : bs[wi - 15];
        if (lane == wi) myLogit = sum + bias;
    }

    // softmax over lanes 0..14
    float v15 = (lane < 15) ? myLogit : -1e30f;
    float m15 = v15;
#pragma unroll
    for (int off = 16; off; off >>= 1) m15 = fmaxf(m15, __shfl_xor_sync(0xffffffffu, m15, off));
    float e = (lane < 15) ? __expf(myLogit - m15) : 0.f;
    float ssum = e;
#pragma unroll
    for (int off = 16; off; off >>= 1) ssum += __shfl_xor_sync(0xffffffffu, ssum, off);
    float inv = 1.f / ssum;

    // top-3 (remove exactly one lane per pick -> matches jax top_k with ties)
    float vv = e;
    float gsum3 = 0.f;
    for (int pick = 0; pick < 3; pick++) {
        float pm = vv;
#pragma unroll
        for (int off = 16; off; off >>= 1) pm = fmaxf(pm, __shfl_xor_sync(0xffffffffu, pm, off));
        gsum3 += pm;
        unsigned eqm = __ballot_sync(0xffffffffu, vv == pm);
        int first = __ffs(eqm) - 1;
        if (lane == first) vv = -1.f;
    }
    gsum3 *= inv;

    float l15 = __shfl_sync(0xffffffffu, myLogit, 15);
    float l16 = __shfl_sync(0xffffffffu, myLogit, 16);
    float m2 = fmaxf(l15, l16);
    float e0 = __expf(l15 - m2), e1 = __expf(l16 - m2);
    float s2 = e0 + e1;
    float s0 = e0 / s2, s1 = e1 / s2;

    if (lane == 0)
        g_gate[tok] = 2.f * s0 * (s0 + s1) + 6.f * s1 * gsum3;
}

// ===========================================================================
// Kernel 4: output projection.  out = (g .* h) @ Wp^T + bp
// grid = (32, 8), 256 threads.  128x128x16 tiles.
// ===========================================================================
__global__ __launch_bounds__(256) void proj_gemm(
    const float* __restrict__ Wp, const float* __restrict__ bp,
    float* __restrict__ out)
{
    __shared__ float As[16][128];
    __shared__ float Bs[16][128];

    const int tid = threadIdx.x;
    const int tx = tid & 15, ty = tid >> 4;
    const int m0 = blockIdx.x * 128;
    const int n0 = blockIdx.y * 128;
    const int lr = tid >> 1;
    const int lk = (tid & 1) * 8;

    float acc[8][8];
#pragma unroll
    for (int i = 0; i < 8; i++)
#pragma unroll
        for (int j = 0; j < 8; j++) acc[i][j] = 0.f;

    const float gr = g_gate[m0 + lr];
    const float* aPtr = g_h + (m0 + lr) * DIM + lk;
    const float* bPtr = Wp + (n0 + lr) * DIM + lk;

    for (int k0 = 0; k0 < DIM; k0 += 16) {
#pragma unroll
        for (int h = 0; h < 2; h++) {
            float4 av  = *(const float4*)(aPtr + k0 + h * 4);
            float4 bv4 = *(const float4*)(bPtr + k0 + h * 4);
            As[lk + h * 4 + 0][lr] = av.x * gr;  As[lk + h * 4 + 1][lr] = av.y * gr;
            As[lk + h * 4 + 2][lr] = av.z * gr;  As[lk + h * 4 + 3][lr] = av.w * gr;
            Bs[lk + h * 4 + 0][lr] = bv4.x; Bs[lk + h * 4 + 1][lr] = bv4.y;
            Bs[lk + h * 4 + 2][lr] = bv4.z; Bs[lk + h * 4 + 3][lr] = bv4.w;
        }
        __syncthreads();
#pragma unroll
        for (int kk = 0; kk < 16; kk++) {
            float4 a0 = *(const float4*)&As[kk][8 * ty];
            float4 a1 = *(const float4*)&As[kk][8 * ty + 4];
            float4 b0 = *(const float4*)&Bs[kk][8 * tx];
            float4 b1 = *(const float4*)&Bs[kk][8 * tx + 4];
            float ar[8] = {a0.x, a0.y, a0.z, a0.w, a1.x, a1.y, a1.z, a1.w};
            float br_[8] = {b0.x, b0.y, b0.z, b0.w, b1.x, b1.y, b1.z, b1.w};
#pragma unroll
            for (int i = 0; i < 8; i++)
#pragma unroll
                for (int j = 0; j < 8; j++) acc[i][j] += ar[i] * br_[j];
        }
        __syncthreads();
    }

#pragma unroll
    for (int i = 0; i < 8; i++) {
        int m = m0 + 8 * ty + i;
#pragma unroll
        for (int j4 = 0; j4 < 2; j4++) {
            int col = n0 + 8 * tx + j4 * 4;
            float4 vo;
            vo.x = acc[i][j4 * 4 + 0] + bp[col + 0];
            vo.y = acc[i][j4 * 4 + 1] + bp[col + 1];
            vo.z = acc[i][j4 * 4 + 2] + bp[col + 2];
            vo.w = acc[i][j4 * 4 + 3] + bp[col + 3];
            *(float4*)&out[m * DIM + col] = vo;
        }
    }
}

// ===========================================================================
extern "C" void kernel_launch(void* const* d_in, const int* in_sizes, int n_in,
                              void* d_out, int out_size)
{
    const float* x  = (const float*)d_in[0];
    const float* Wq = (const float*)d_in[1];
    const float* bq = (const float*)d_in[2];
    const float* Wk = (const float*)d_in[3];
    const float* bk = (const float*)d_in[4];
    const float* Wv = (const float*)d_in[5];
    const float* bv = (const float*)d_in[6];
    const float* Wp = (const float*)d_in[7];
    const float* bp = (const float*)d_in[8];
    const float* Wr = (const float*)d_in[9];
    const float* br = (const float*)d_in[10];
    const float* Ws = (const float*)d_in[11];
    const float* bs = (const float*)d_in[12];
    const float* tp = (const float*)d_in[13];
    const float* qe = (const float*)d_in[14];
    float* out = (float*)d_out;

    cudaFuncSetAttribute(attn_kernel,
                         cudaFuncAttributeMaxDynamicSharedMemorySize, ATTN_SMEM);

    qkv_gemm<<<dim3(32, 24), 256>>>(x, Wq, bq, Wk, bk, Wv, bv);
    attn_kernel<<<dim3(32, 32), 256, ATTN_SMEM>>>(tp, qe);
    gate_kernel<<<512, 256>>>(Wr, br, Ws, bs);
    proj_gemm<<<dim3(32, 8), 256>>>(Wp, bp, out);
}

// round 10
// speedup vs baseline: 2.4871x; 2.4871x over previous
#include <cuda_runtime.h>
#include <math.h>
#include <stdint.h>

#define B_SZ   2
#define NTOK   2048
#define DIM    1024
#define NH     16
#define HD     64
#define M_TOT  (B_SZ * NTOK)      // 4096
#define QT     128                // attention query tile

// ---------------- scratch (device globals; no runtime allocation) ----------
__device__ float g_q[B_SZ * NH * NTOK * HD];   // [B,H,N,hd]
__device__ float g_k[B_SZ * NH * NTOK * HD];
__device__ float g_v[B_SZ * NH * NTOK * HD];
__device__ float g_h[M_TOT * DIM];             // attention output [B,N,DIM]
__device__ float g_gate[M_TOT];                // per-token gate scalar

// ---------------- tf32 helpers --------------------------------------------
__device__ __forceinline__ uint32_t f2tf32(float x) {
    uint32_t r;
    asm("cvt.rna.tf32.f32 %0, %1;" : "=r"(r) : "f"(x));
    return r;
}

// D(16x8) += A(16x8,row) * B(8x8,col);  tf32 in, f32 accum
// A regs: a0=(g,t) a1=(g+8,t) a2=(g,t+4) a3=(g+8,t+4)  [CUTLASS SM80 layout]
// B regs: b0=(k=t,n=g) b1=(k=t+4,n=g)
// C regs: c0=(g,2t) c1=(g,2t+1) c2=(g+8,2t) c3=(g+8,2t+1)
__device__ __forceinline__ void mma_tf32(float* c, const uint32_t* a, const uint32_t* b) {
    asm volatile(
        "mma.sync.aligned.m16n8k8.row.col.f32.tf32.tf32.f32 "
        "{%0,%1,%2,%3}, {%4,%5,%6,%7}, {%8,%9}, {%0,%1,%2,%3};"
        : "+f"(c[0]), "+f"(c[1]), "+f"(c[2]), "+f"(c[3])
        : "r"(a[0]), "r"(a[1]), "r"(a[2]), "r"(a[3]), "r"(b[0]), "r"(b[1]));
}

// ===========================================================================
// Kernel 1: fused QKV projection (tf32 tensor cores).
// Y = x @ W^T + b for Wq/Wk/Wv, scattered to [B,H,N,hd].
// Block tile 128x128, K-step 16.  8 warps as 2(M)x4(N); warp tile 64x32.
// grid = (32, 24), 256 threads.
// ===========================================================================
__global__ __launch_bounds__(256) void qkv_gemm(
    const float* __restrict__ x,
    const float* __restrict__ Wq, const float* __restrict__ bq,
    const float* __restrict__ Wk, const float* __restrict__ bk,
    const float* __restrict__ Wv, const float* __restrict__ bv)
{
    __shared__ uint32_t As[128][20];   // [m][k], stride 20 words (bank-perfect)
    __shared__ uint32_t Bs[128][20];   // [n][k]

    const int tid  = threadIdx.x;
    const int warp = tid >> 5, lane = tid & 31;
    const int g = lane >> 2, t = lane & 3;
    const int wm = (warp >> 2) * 64;        // 0 or 64
    const int wn = (warp & 3) * 32;         // 0,32,64,96

    const int m0 = blockIdx.x * 128;
    const int n0 = blockIdx.y * 128;
    const int seg = n0 >> 10;
    const float* W    = (seg == 0) ? Wq : (seg == 1) ? Wk : Wv;
    const float* bias = (seg == 0) ? bq : (seg == 1) ? bk : bv;
    float* outp       = (seg == 0) ? g_q : (seg == 1) ? g_k : g_v;
    const int ncol0 = n0 & 1023;

    const int row = tid >> 1;               // 0..127
    const int q4  = (tid & 1) * 8;          // 0 or 8

    float acc[4][4][4];                     // [m-tile][n-tile][reg]
#pragma unroll
    for (int i = 0; i < 4; i++)
#pragma unroll
        for (int j = 0; j < 4; j++)
#pragma unroll
            for (int r = 0; r < 4; r++) acc[i][j][r] = 0.f;

    const float* aPtr = x + (m0 + row) * DIM;
    const float* bPtr = W + (ncol0 + row) * DIM;

    for (int k0 = 0; k0 < DIM; k0 += 16) {
        float4 a0 = *(const float4*)(aPtr + k0 + q4);
        float4 a1 = *(const float4*)(aPtr + k0 + q4 + 4);
        float4 b0 = *(const float4*)(bPtr + k0 + q4);
        float4 b1 = *(const float4*)(bPtr + k0 + q4 + 4);
        *(uint4*)&As[row][q4]     = make_uint4(f2tf32(a0.x), f2tf32(a0.y), f2tf32(a0.z), f2tf32(a0.w));
        *(uint4*)&As[row][q4 + 4] = make_uint4(f2tf32(a1.x), f2tf32(a1.y), f2tf32(a1.z), f2tf32(a1.w));
        *(uint4*)&Bs[row][q4]     = make_uint4(f2tf32(b0.x), f2tf32(b0.y), f2tf32(b0.z), f2tf32(b0.w));
        *(uint4*)&Bs[row][q4 + 4] = make_uint4(f2tf32(b1.x), f2tf32(b1.y), f2tf32(b1.z), f2tf32(b1.w));
        __syncthreads();

#pragma unroll
        for (int kk = 0; kk < 16; kk += 8) {
            uint32_t afr[4][4], bfr[4][2];
#pragma unroll
            for (int mi = 0; mi < 4; mi++) {
                int rb = wm + mi * 16;
                afr[mi][0] = As[rb + g][kk + t];
                afr[mi][1] = As[rb + g + 8][kk + t];
                afr[mi][2] = As[rb + g][kk + t + 4];
                afr[mi][3] = As[rb + g + 8][kk + t + 4];
            }
#pragma unroll
            for (int ni = 0; ni < 4; ni++) {
                int nb = wn + ni * 8;
                bfr[ni][0] = Bs[nb + g][kk + t];
                bfr[ni][1] = Bs[nb + g][kk + t + 4];
            }
#pragma unroll
            for (int mi = 0; mi < 4; mi++)
#pragma unroll
                for (int ni = 0; ni < 4; ni++)
                    mma_tf32(acc[mi][ni], afr[mi], bfr[ni]);
        }
        __syncthreads();
    }

    // epilogue: bias + scatter to [B,H,N,hd]
#pragma unroll
    for (int mi = 0; mi < 4; mi++) {
#pragma unroll
        for (int h = 0; h < 2; h++) {
            int m = m0 + wm + mi * 16 + g + 8 * h;
            int bb = m >> 11, n = m & 2047;
#pragma unroll
            for (int ni = 0; ni < 4; ni++) {
                int col = ncol0 + wn + ni * 8 + 2 * t;
                int head = col >> 6, d = col & 63;
                float2 vo;
                vo.x = acc[mi][ni][2 * h + 0] + bias[col + 0];
                vo.y = acc[mi][ni][2 * h + 1] + bias[col + 1];
                *(float2*)&outp[(((bb * NH + head) * NTOK) + n) * HD + d] = vo;
            }
        }
    }
}

// ===========================================================================
// Kernel 2: flash attention, tf32 tensor cores, fused Q preprocessing.
// Q-tile 128, key-tile 64.  8 warps x 16 query rows; EACH WARP OWNS ALL 64
// KEYS for its rows, so the online softmax is entirely warp-local (this is
// the R9 bug fix).  Ps is warp-private (syncwarp only between write & read).
// grid = (NTOK/128 = 16, B*H = 32), 256 threads.
// ===========================================================================
#define ATTN_SMEM ((QT * 68 * 2 + 64 * 68 + 64 * 72) * 4)   // Qs,Ps | Ks | Vs

__global__ __launch_bounds__(256, 1) void attn_kernel(
    const float* __restrict__ temperature,
    const float* __restrict__ qe)
{
    extern __shared__ uint32_t smu[];
    uint32_t* Qs = smu;                 // [q][d]   stride 68, QT rows
    uint32_t* Ks = Qs + QT * 68;        // [key][d] stride 68, 64 rows
    uint32_t* Vs = Ks + 64 * 68;        // [key][d] stride 72, 64 rows
    uint32_t* Ps = Vs + 64 * 72;        // [q][key] stride 68, QT rows

    const int tid  = threadIdx.x;
    const int warp = tid >> 5, lane = tid & 31;
    const int g = lane >> 2, t = lane & 3;
    const int wq = warp * 16;           // this warp's query-row base

    const int bh = blockIdx.y;
    const int b = bh >> 4, hh = bh & 15;
    const int q0 = blockIdx.x * QT;

    const float* qbase = g_q + (bh * NTOK + q0) * HD;
    const float* kbase = g_k + (long)bh * NTOK * HD;
    const float* vbase = g_v + (long)bh * NTOK * HD;

    // ---- Q preprocess: (q/||q|| + qe) * softplus(t)/8, cvt tf32
    // r = tid>>1 (0..127), each thread handles 32 cols (half a row)
    {
        int r  = tid >> 1;
        int c0 = (tid & 1) * 32;
        float4 v[8];
#pragma unroll
        for (int f = 0; f < 8; f++)
            v[f] = *(const float4*)(qbase + r * HD + c0 + f * 4);
        float ss = 0.f;
#pragma unroll
        for (int f = 0; f < 8; f++)
            ss += v[f].x * v[f].x + v[f].y * v[f].y + v[f].z * v[f].z + v[f].w * v[f].w;
        ss += __shfl_xor_sync(0xffffffffu, ss, 1);   // partner holds other half
        float inv = rsqrtf(ss);
        float tt = temperature[hh];
        float sp = (tt > 20.f) ? tt : log1pf(__expf(tt));
        float tc = sp * 0.125f;                      // /sqrt(64)
        const float* qeh = qe + hh * HD;
#pragma unroll
        for (int f = 0; f < 8; f++) {
            int d = c0 + f * 4;
            uint4 u;
            u.x = f2tf32((v[f].x * inv + qeh[d + 0]) * tc);
            u.y = f2tf32((v[f].y * inv + qeh[d + 1]) * tc);
            u.z = f2tf32((v[f].z * inv + qeh[d + 2]) * tc);
            u.w = f2tf32((v[f].w * inv + qeh[d + 3]) * tc);
            *(uint4*)&Qs[r * 68 + d] = u;
        }
    }
    // (first __syncthreads below covers Qs visibility before any S-mma)

    float oacc[8][4];                   // [d-block 0..7][reg]
    float mi[2], li[2];                 // rows g, g+8
#pragma unroll
    for (int i = 0; i < 8; i++)
#pragma unroll
        for (int r = 0; r < 4; r++) oacc[i][r] = 0.f;
    mi[0] = mi[1] = -1e30f;
    li[0] = li[1] = 0.f;

    for (int kt = 0; kt < NTOK / 64; kt++) {
        // ---- load K,V tiles (cvt tf32): 64 keys x 64 d over 256 threads
        {
            int j = tid >> 2, c4 = tid & 3;
            const float* kp = kbase + (kt * 64 + j) * HD + c4 * 16;
            const float* vp = vbase + (kt * 64 + j) * HD + c4 * 16;
#pragma unroll
            for (int f = 0; f < 4; f++) {
                float4 kv = *(const float4*)(kp + f * 4);
                float4 vv = *(const float4*)(vp + f * 4);
                int d = c4 * 16 + f * 4;
                *(uint4*)&Ks[j * 68 + d] = make_uint4(f2tf32(kv.x), f2tf32(kv.y), f2tf32(kv.z), f2tf32(kv.w));
                *(uint4*)&Vs[j * 72 + d] = make_uint4(f2tf32(vv.x), f2tf32(vv.y), f2tf32(vv.z), f2tf32(vv.w));
            }
        }
        __syncthreads();

        // ---- S = Q K^T : warp tile 16(q) x 64(key), 8 k8 steps over d
        float sacc[8][4];
#pragma unroll
        for (int i = 0; i < 8; i++)
#pragma unroll
            for (int r = 0; r < 4; r++) sacc[i][r] = 0.f;

#pragma unroll
        for (int kk = 0; kk < 64; kk += 8) {
            uint32_t afr[4], bfr[8][2];
            afr[0] = Qs[(wq + g) * 68 + kk + t];
            afr[1] = Qs[(wq + g + 8) * 68 + kk + t];
            afr[2] = Qs[(wq + g) * 68 + kk + t + 4];
            afr[3] = Qs[(wq + g + 8) * 68 + kk + t + 4];
#pragma unroll
            for (int ni = 0; ni < 8; ni++) {
                bfr[ni][0] = Ks[(ni * 8 + g) * 68 + kk + t];
                bfr[ni][1] = Ks[(ni * 8 + g) * 68 + kk + t + 4];
            }
#pragma unroll
            for (int ni = 0; ni < 8; ni++)
                mma_tf32(sacc[ni], afr, bfr[ni]);
        }

        // ---- online softmax, fully warp-local (all 64 keys in-warp)
#pragma unroll
        for (int i = 0; i < 2; i++) {
            int idx = 2 * i;            // regs idx, idx+1 belong to row g+8i
            float rm = -1e30f;
#pragma unroll
            for (int ni = 0; ni < 8; ni++)
                rm = fmaxf(rm, fmaxf(sacc[ni][idx], sacc[ni][idx + 1]));
            rm = fmaxf(rm, __shfl_xor_sync(0xffffffffu, rm, 1));
            rm = fmaxf(rm, __shfl_xor_sync(0xffffffffu, rm, 2));
            float mnew = fmaxf(mi[i], rm);
            float corr = __expf(mi[i] - mnew);
            float rs = 0.f;
#pragma unroll
            for (int ni = 0; ni < 8; ni++) {
                float p0 = __expf(sacc[ni][idx]     - mnew);
                float p1 = __expf(sacc[ni][idx + 1] - mnew);
                rs += p0 + p1;
                *(uint2*)&Ps[(wq + g + 8 * i) * 68 + ni * 8 + 2 * t] =
                    make_uint2(f2tf32(p0), f2tf32(p1));
            }
            rs += __shfl_xor_sync(0xffffffffu, rs, 1);
            rs += __shfl_xor_sync(0xffffffffu, rs, 2);
            li[i] = li[i] * corr + rs;
            mi[i] = mnew;
#pragma unroll
            for (int ni = 0; ni < 8; ni++) {
                oacc[ni][idx]     *= corr;
                oacc[ni][idx + 1] *= corr;
            }
        }
        __syncwarp();                   // Ps is warp-private: warp-sync suffices

        // ---- O += P V : warp tile 16(q) x 64(d), 8 k8 steps over keys
#pragma unroll
        for (int kk = 0; kk < 64; kk += 8) {
            uint32_t afr[4], bfr[8][2];
            afr[0] = Ps[(wq + g) * 68 + kk + t];
            afr[1] = Ps[(wq + g + 8) * 68 + kk + t];
            afr[2] = Ps[(wq + g) * 68 + kk + t + 4];
            afr[3] = Ps[(wq + g + 8) * 68 + kk + t + 4];
#pragma unroll
            for (int ni = 0; ni < 8; ni++) {
                bfr[ni][0] = Vs[(kk + t) * 72 + ni * 8 + g];
                bfr[ni][1] = Vs[(kk + t + 4) * 72 + ni * 8 + g];
            }
#pragma unroll
            for (int ni = 0; ni < 8; ni++)
                mma_tf32(oacc[ni], afr, bfr[ni]);
        }
        __syncthreads();                // protect Ks/Vs before next load
    }

    // ---- epilogue: /l, write h [B,N,DIM]
#pragma unroll
    for (int i = 0; i < 2; i++) {
        int idx = 2 * i;
        float invl = 1.0f / li[i];
        int n = q0 + wq + g + 8 * i;
#pragma unroll
        for (int ni = 0; ni < 8; ni++) {
            int col = ni * 8 + 2 * t;
            float2 vo;
            vo.x = oacc[ni][idx]     * invl;
            vo.y = oacc[ni][idx + 1] * invl;
            *(float2*)&g_h[(b * NTOK + n) * DIM + hh * HD + col] = vo;
        }
    }
}

// ===========================================================================
// Kernel 3: gating -> scalar g per token (fp32, one warp per token).
// ===========================================================================
__global__ __launch_bounds__(256) void gate_kernel(
    const float* __restrict__ Wr, const float* __restrict__ br,
    const float* __restrict__ Ws, const float* __restrict__ bs)
{
    const int warp = threadIdx.x >> 5, lane = threadIdx.x & 31;
    const int tok = blockIdx.x * 8 + warp;
    const float* hrow = g_h + tok * DIM;

    float hv[32];
#pragma unroll
    for (int kk = 0; kk < 32; kk++) hv[kk] = hrow[lane + 32 * kk];

    float myLogit = -1e30f;
#pragma unroll
    for (int wi = 0; wi < 17; wi++) {
        const float* wrow = (wi < 15) ? (Wr + wi * DIM) : (Ws + (wi - 15) * DIM);
        float sum = 0.f;
#pragma unroll
        for (int kk = 0; kk < 32; kk++) sum += hv[kk] * wrow[lane + 32 * kk];
#pragma unroll
        for (int off = 16; off; off >>= 1) sum += __shfl_xor_sync(0xffffffffu, sum, off);
        float bias = (wi < 15) ? br[wi] : bs[wi - 15];
        if (lane == wi) myLogit = sum + bias;
    }

    float v15 = (lane < 15) ? myLogit : -1e30f;
    float m15 = v15;
#pragma unroll
    for (int off = 16; off; off >>= 1) m15 = fmaxf(m15, __shfl_xor_sync(0xffffffffu, m15, off));
    float e = (lane < 15) ? __expf(myLogit - m15) : 0.f;
    float ssum = e;
#pragma unroll
    for (int off = 16; off; off >>= 1) ssum += __shfl_xor_sync(0xffffffffu, ssum, off);
    float inv = 1.f / ssum;

    float vv = e;
    float gsum3 = 0.f;
    for (int pick = 0; pick < 3; pick++) {
        float pm = vv;
#pragma unroll
        for (int off = 16; off; off >>= 1) pm = fmaxf(pm, __shfl_xor_sync(0xffffffffu, pm, off));
        gsum3 += pm;
        unsigned eqm = __ballot_sync(0xffffffffu, vv == pm);
        int first = __ffs(eqm) - 1;
        if (lane == first) vv = -1.f;
    }
    gsum3 *= inv;

    float l15 = __shfl_sync(0xffffffffu, myLogit, 15);
    float l16 = __shfl_sync(0xffffffffu, myLogit, 16);
    float m2 = fmaxf(l15, l16);
    float e0 = __expf(l15 - m2), e1 = __expf(l16 - m2);
    float s2 = e0 + e1;
    float s0 = e0 / s2, s1 = e1 / s2;

    if (lane == 0)
        g_gate[tok] = 2.f * s0 * (s0 + s1) + 6.f * s1 * gsum3;
}

// ===========================================================================
// Kernel 4: output projection (tf32).  out = (g .* h) @ Wp^T + bp
// grid = (32, 8), 256 threads.
// ===========================================================================
__global__ __launch_bounds__(256) void proj_gemm(
    const float* __restrict__ Wp, const float* __restrict__ bp,
    float* __restrict__ out)
{
    __shared__ uint32_t As[128][20];
    __shared__ uint32_t Bs[128][20];

    const int tid  = threadIdx.x;
    const int warp = tid >> 5, lane = tid & 31;
    const int g = lane >> 2, t = lane & 3;
    const int wm = (warp >> 2) * 64;
    const int wn = (warp & 3) * 32;

    const int m0 = blockIdx.x * 128;
    const int n0 = blockIdx.y * 128;
    const int row = tid >> 1;
    const int q4  = (tid & 1) * 8;

    float acc[4][4][4];
#pragma unroll
    for (int i = 0; i < 4; i++)
#pragma unroll
        for (int j = 0; j < 4; j++)
#pragma unroll
            for (int r = 0; r < 4; r++) acc[i][j][r] = 0.f;

    const float gr = g_gate[m0 + row];
    const float* aPtr = g_h + (m0 + row) * DIM;
    const float* bPtr = Wp + (n0 + row) * DIM;

    for (int k0 = 0; k0 < DIM; k0 += 16) {
        float4 a0 = *(const float4*)(aPtr + k0 + q4);
        float4 a1 = *(const float4*)(aPtr + k0 + q4 + 4);
        float4 b0 = *(const float4*)(bPtr + k0 + q4);
        float4 b1 = *(const float4*)(bPtr + k0 + q4 + 4);
        *(uint4*)&As[row][q4]     = make_uint4(f2tf32(a0.x * gr), f2tf32(a0.y * gr), f2tf32(a0.z * gr), f2tf32(a0.w * gr));
        *(uint4*)&As[row][q4 + 4] = make_uint4(f2tf32(a1.x * gr), f2tf32(a1.y * gr), f2tf32(a1.z * gr), f2tf32(a1.w * gr));
        *(uint4*)&Bs[row][q4]     = make_uint4(f2tf32(b0.x), f2tf32(b0.y), f2tf32(b0.z), f2tf32(b0.w));
        *(uint4*)&Bs[row][q4 + 4] = make_uint4(f2tf32(b1.x), f2tf32(b1.y), f2tf32(b1.z), f2tf32(b1.w));
        __syncthreads();

#pragma unroll
        for (int kk = 0; kk < 16; kk += 8) {
            uint32_t afr[4][4], bfr[4][2];
#pragma unroll
            for (int mi = 0; mi < 4; mi++) {
                int rb = wm + mi * 16;
                afr[mi][0] = As[rb + g][kk + t];
                afr[mi][1] = As[rb + g + 8][kk + t];
                afr[mi][2] = As[rb + g][kk + t + 4];
                afr[mi][3] = As[rb + g + 8][kk + t + 4];
            }
#pragma unroll
            for (int ni = 0; ni < 4; ni++) {
                int nb = wn + ni * 8;
                bfr[ni][0] = Bs[nb + g][kk + t];
                bfr[ni][1] = Bs[nb + g][kk + t + 4];
            }
#pragma unroll
            for (int mi = 0; mi < 4; mi++)
#pragma unroll
                for (int ni = 0; ni < 4; ni++)
                    mma_tf32(acc[mi][ni], afr[mi], bfr[ni]);
        }
        __syncthreads();
    }

#pragma unroll
    for (int mi = 0; mi < 4; mi++) {
#pragma unroll
        for (int h = 0; h < 2; h++) {
            int m = m0 + wm + mi * 16 + g + 8 * h;
#pragma unroll
            for (int ni = 0; ni < 4; ni++) {
                int col = n0 + wn + ni * 8 + 2 * t;
                float2 vo;
                vo.x = acc[mi][ni][2 * h + 0] + bp[col + 0];
                vo.y = acc[mi][ni][2 * h + 1] + bp[col + 1];
                *(float2*)&out[m * DIM + col] = vo;
            }
        }
    }
}

// ===========================================================================
extern "C" void kernel_launch(void* const* d_in, const int* in_sizes, int n_in,
                              void* d_out, int out_size)
{
    const float* x  = (const float*)d_in[0];
    const float* Wq = (const float*)d_in[1];
    const float* bq = (const float*)d_in[2];
    const float* Wk = (const float*)d_in[3];
    const float* bk = (const float*)d_in[4];
    const float* Wv = (const float*)d_in[5];
    const float* bv = (const float*)d_in[6];
    const float* Wp = (const float*)d_in[7];
    const float* bp = (const float*)d_in[8];
    const float* Wr = (const float*)d_in[9];
    const float* br = (const float*)d_in[10];
    const float* Ws = (const float*)d_in[11];
    const float* bs = (const float*)d_in[12];
    const float* tp = (const float*)d_in[13];
    const float* qe = (const float*)d_in[14];
    float* out = (float*)d_out;

    cudaFuncSetAttribute(attn_kernel,
                         cudaFuncAttributeMaxDynamicSharedMemorySize, ATTN_SMEM);

    qkv_gemm<<<dim3(32, 24), 256>>>(x, Wq, bq, Wk, bk, Wv, bv);
    attn_kernel<<<dim3(16, 32), 256, ATTN_SMEM>>>(tp, qe);
    gate_kernel<<<512, 256>>>(Wr, br, Ws, bs);
    proj_gemm<<<dim3(32, 8), 256>>>(Wp, bp, out);
}

// round 11
// speedup vs baseline: 2.5091x; 1.0088x over previous
#include <cuda_runtime.h>
#include <math.h>
#include <stdint.h>

#define B_SZ   2
#define NTOK   2048
#define DIM    1024
#define NH     16
#define HD     64
#define M_TOT  (B_SZ * NTOK)      // 4096
#define QT     256                // attention query tile

// ---------------- scratch (device globals; no runtime allocation) ----------
__device__ float g_q[B_SZ * NH * NTOK * HD];   // [B,H,N,hd]
__device__ float g_k[B_SZ * NH * NTOK * HD];
__device__ float g_v[B_SZ * NH * NTOK * HD];
__device__ float g_h[M_TOT * DIM];             // attention output [B,N,DIM]
__device__ float g_gate[M_TOT];                // per-token gate scalar

// ---------------- tf32 helpers --------------------------------------------
__device__ __forceinline__ uint32_t f2tf32(float x) {
    uint32_t r;
    asm("cvt.rna.tf32.f32 %0, %1;" : "=r"(r) : "f"(x));
    return r;
}
__device__ __forceinline__ uint4 cvt4(float4 v) {
    return make_uint4(f2tf32(v.x), f2tf32(v.y), f2tf32(v.z), f2tf32(v.w));
}

// D(16x8) += A(16x8,row) * B(8x8,col);  tf32 in, f32 accum
// A regs: a0=(g,t) a1=(g+8,t) a2=(g,t+4) a3=(g+8,t+4)
// B regs: b0=(k=t,n=g) b1=(k=t+4,n=g)
// C regs: c0=(g,2t) c1=(g,2t+1) c2=(g+8,2t) c3=(g+8,2t+1)
__device__ __forceinline__ void mma_tf32(float* c, const uint32_t* a, const uint32_t* b) {
    asm volatile(
        "mma.sync.aligned.m16n8k8.row.col.f32.tf32.tf32.f32 "
        "{%0,%1,%2,%3}, {%4,%5,%6,%7}, {%8,%9}, {%0,%1,%2,%3};"
        : "+f"(c[0]), "+f"(c[1]), "+f"(c[2]), "+f"(c[3])
        : "r"(a[0]), "r"(a[1]), "r"(a[2]), "r"(a[3]), "r"(b[0]), "r"(b[1]));
}

// ===========================================================================
// Kernel 1: fused QKV projection (tf32, pipelined double buffer).
// Block 128x128, 4 warps (warp tile 64x64), K-step 16, 64 iterations.
// grid = (32, 24), 128 threads.
// ===========================================================================
__global__ __launch_bounds__(128) void qkv_gemm(
    const float* __restrict__ x,
    const float* __restrict__ Wq, const float* __restrict__ bq,
    const float* __restrict__ Wk, const float* __restrict__ bk,
    const float* __restrict__ Wv, const float* __restrict__ bv)
{
    __shared__ uint32_t As[2][128][20];
    __shared__ uint32_t Bs[2][128][20];

    const int tid  = threadIdx.x;
    const int warp = tid >> 5, lane = tid & 31;
    const int g = lane >> 2, t = lane & 3;
    const int wm = (warp >> 1) * 64;        // 0 or 64
    const int wn = (warp & 1) * 64;         // 0 or 64

    const int m0 = blockIdx.x * 128;
    const int n0 = blockIdx.y * 128;
    const int seg = n0 >> 10;
    const float* W    = (seg == 0) ? Wq : (seg == 1) ? Wk : Wv;
    const float* bias = (seg == 0) ? bq : (seg == 1) ? bk : bv;
    float* outp       = (seg == 0) ? g_q : (seg == 1) ? g_k : g_v;
    const int ncol0 = n0 & 1023;

    const int row = tid;                    // 0..127

    float acc[4][8][4];
#pragma unroll
    for (int i = 0; i < 4; i++)
#pragma unroll
        for (int j = 0; j < 8; j++)
#pragma unroll
            for (int r = 0; r < 4; r++) acc[i][j][r] = 0.f;

    const float* aPtr = x + (m0 + row) * DIM;
    const float* bPtr = W + (ncol0 + row) * DIM;

    float4 sa[4], sb[4];
#pragma unroll
    for (int f = 0; f < 4; f++) {
        sa[f] = *(const float4*)(aPtr + f * 4);
        sb[f] = *(const float4*)(bPtr + f * 4);
    }
#pragma unroll
    for (int f = 0; f < 4; f++) {
        *(uint4*)&As[0][row][f * 4] = cvt4(sa[f]);
        *(uint4*)&Bs[0][row][f * 4] = cvt4(sb[f]);
    }
    __syncthreads();

    for (int kt = 0; kt < 64; kt++) {
        const int cur = kt & 1;
        if (kt < 63) {
            const float* ap = aPtr + (kt + 1) * 16;
            const float* bp = bPtr + (kt + 1) * 16;
#pragma unroll
            for (int f = 0; f < 4; f++) {
                sa[f] = *(const float4*)(ap + f * 4);
                sb[f] = *(const float4*)(bp + f * 4);
            }
        }

#pragma unroll
        for (int kk = 0; kk < 16; kk += 8) {
            uint32_t afr[4][4], bfr[8][2];
#pragma unroll
            for (int mi = 0; mi < 4; mi++) {
                int rb = wm + mi * 16;
                afr[mi][0] = As[cur][rb + g][kk + t];
                afr[mi][1] = As[cur][rb + g + 8][kk + t];
                afr[mi][2] = As[cur][rb + g][kk + t + 4];
                afr[mi][3] = As[cur][rb + g + 8][kk + t + 4];
            }
#pragma unroll
            for (int ni = 0; ni < 8; ni++) {
                int nb = wn + ni * 8;
                bfr[ni][0] = Bs[cur][nb + g][kk + t];
                bfr[ni][1] = Bs[cur][nb + g][kk + t + 4];
            }
#pragma unroll
            for (int mi = 0; mi < 4; mi++)
#pragma unroll
                for (int ni = 0; ni < 8; ni++)
                    mma_tf32(acc[mi][ni], afr[mi], bfr[ni]);
        }

        if (kt < 63) {
            const int nxt = cur ^ 1;
#pragma unroll
            for (int f = 0; f < 4; f++) {
                *(uint4*)&As[nxt][row][f * 4] = cvt4(sa[f]);
                *(uint4*)&Bs[nxt][row][f * 4] = cvt4(sb[f]);
            }
        }
        __syncthreads();
    }

    // epilogue: bias + scatter to [B,H,N,hd]
#pragma unroll
    for (int mi = 0; mi < 4; mi++) {
#pragma unroll
        for (int h = 0; h < 2; h++) {
            int m = m0 + wm + mi * 16 + g + 8 * h;
            int bb = m >> 11, n = m & 2047;
#pragma unroll
            for (int ni = 0; ni < 8; ni++) {
                int col = ncol0 + wn + ni * 8 + 2 * t;
                int head = col >> 6, d = col & 63;
                float2 vo;
                vo.x = acc[mi][ni][2 * h + 0] + bias[col + 0];
                vo.y = acc[mi][ni][2 * h + 1] + bias[col + 1];
                *(float2*)&outp[(((bb * NH + head) * NTOK) + n) * HD + d] = vo;
            }
        }
    }
}

// ===========================================================================
// Kernel 2: flash attention, tf32 mma, pipelined K/V double buffer.
// Q-tile 256, key-tile 64.  8 warps x 32 query rows; each warp owns all 64
// keys for its rows (warp-local online softmax).
// grid = (NTOK/256 = 8, B*H = 32), 256 threads, ~206KB dynamic smem.
// ===========================================================================
#define ATTN_SMEM ((QT * 68 * 2 + 2 * 64 * 68 + 2 * 64 * 72) * 4)

__global__ __launch_bounds__(256, 1) void attn_kernel(
    const float* __restrict__ temperature,
    const float* __restrict__ qe)
{
    extern __shared__ uint32_t smu[];
    uint32_t* Qs = smu;                       // [q][d]   stride 68, QT rows
    uint32_t* Ks = Qs + QT * 68;              // [2][key][d] stride 68
    uint32_t* Vs = Ks + 2 * 64 * 68;          // [2][key][d] stride 72
    uint32_t* Ps = Vs + 2 * 64 * 72;          // [q][key] stride 68, QT rows

    const int tid  = threadIdx.x;
    const int warp = tid >> 5, lane = tid & 31;
    const int g = lane >> 2, t = lane & 3;
    const int wq = warp * 32;                 // this warp's query-row base

    const int bh = blockIdx.y;
    const int b = bh >> 4, hh = bh & 15;
    const int q0 = blockIdx.x * QT;

    const float* qbase = g_q + (bh * NTOK + q0) * HD;
    const float* kbase = g_k + (long)bh * NTOK * HD;
    const float* vbase = g_v + (long)bh * NTOK * HD;

    // ---- Q preprocess: one full row per thread (r = tid, 0..255)
    {
        int r = tid;
        float qv[64];
        float ss = 0.f;
#pragma unroll
        for (int f = 0; f < 16; f++) {
            float4 v = *(const float4*)(qbase + r * HD + f * 4);
            qv[f * 4 + 0] = v.x; qv[f * 4 + 1] = v.y;
            qv[f * 4 + 2] = v.z; qv[f * 4 + 3] = v.w;
            ss += v.x * v.x + v.y * v.y + v.z * v.z + v.w * v.w;
        }
        float inv = rsqrtf(ss);
        float tt = temperature[hh];
        float sp = (tt > 20.f) ? tt : log1pf(__expf(tt));
        float tc = sp * 0.125f;                      // /sqrt(64)
        const float* qeh = qe + hh * HD;
#pragma unroll
        for (int f = 0; f < 16; f++) {
            uint4 u;
            u.x = f2tf32((qv[f * 4 + 0] * inv + qeh[f * 4 + 0]) * tc);
            u.y = f2tf32((qv[f * 4 + 1] * inv + qeh[f * 4 + 1]) * tc);
            u.z = f2tf32((qv[f * 4 + 2] * inv + qeh[f * 4 + 2]) * tc);
            u.w = f2tf32((qv[f * 4 + 3] * inv + qeh[f * 4 + 3]) * tc);
            *(uint4*)&Qs[r * 68 + f * 4] = u;
        }
    }

    // ---- K/V staging: thread (j = tid>>2, c4 = tid&3) loads 4 float4 each
    const int j  = tid >> 2;
    const int c4 = tid & 3;
    float4 ks[4], vs[4];
    {
        const float* kp = kbase + j * HD + c4 * 16;
        const float* vp = vbase + j * HD + c4 * 16;
#pragma unroll
        for (int f = 0; f < 4; f++) {
            ks[f] = *(const float4*)(kp + f * 4);
            vs[f] = *(const float4*)(vp + f * 4);
        }
    }
#pragma unroll
    for (int f = 0; f < 4; f++) {
        int d = c4 * 16 + f * 4;
        *(uint4*)&Ks[j * 68 + d] = cvt4(ks[f]);
        *(uint4*)&Vs[j * 72 + d] = cvt4(vs[f]);
    }
    __syncthreads();

    float oacc[2][8][4];                 // [m-tile][d-block][reg]
    float mi[2][2], li[2][2];            // [m-tile][row-half]
#pragma unroll
    for (int m = 0; m < 2; m++) {
#pragma unroll
        for (int i = 0; i < 8; i++)
#pragma unroll
            for (int r = 0; r < 4; r++) oacc[m][i][r] = 0.f;
        mi[m][0] = mi[m][1] = -1e30f;
        li[m][0] = li[m][1] = 0.f;
    }

    for (int kt = 0; kt < NTOK / 64; kt++) {
        const int cur = kt & 1;
        uint32_t* Kc = Ks + cur * 64 * 68;
        uint32_t* Vc = Vs + cur * 64 * 72;

        if (kt < NTOK / 64 - 1) {
            const float* kp = kbase + ((kt + 1) * 64 + j) * HD + c4 * 16;
            const float* vp = vbase + ((kt + 1) * 64 + j) * HD + c4 * 16;
#pragma unroll
            for (int f = 0; f < 4; f++) {
                ks[f] = *(const float4*)(kp + f * 4);
                vs[f] = *(const float4*)(vp + f * 4);
            }
        }

        // ---- S = Q K^T : warp tile 32(q) x 64(key)
        float sacc[2][8][4];
#pragma unroll
        for (int m = 0; m < 2; m++)
#pragma unroll
            for (int i = 0; i < 8; i++)
#pragma unroll
                for (int r = 0; r < 4; r++) sacc[m][i][r] = 0.f;

#pragma unroll
        for (int kk = 0; kk < 64; kk += 8) {
            uint32_t afr[2][4], bfr[8][2];
#pragma unroll
            for (int m = 0; m < 2; m++) {
                int rb = wq + m * 16;
                afr[m][0] = Qs[(rb + g) * 68 + kk + t];
                afr[m][1] = Qs[(rb + g + 8) * 68 + kk + t];
                afr[m][2] = Qs[(rb + g) * 68 + kk + t + 4];
                afr[m][3] = Qs[(rb + g + 8) * 68 + kk + t + 4];
            }
#pragma unroll
            for (int ni = 0; ni < 8; ni++) {
                bfr[ni][0] = Kc[(ni * 8 + g) * 68 + kk + t];
                bfr[ni][1] = Kc[(ni * 8 + g) * 68 + kk + t + 4];
            }
#pragma unroll
            for (int m = 0; m < 2; m++)
#pragma unroll
                for (int ni = 0; ni < 8; ni++)
                    mma_tf32(sacc[m][ni], afr[m], bfr[ni]);
        }

        // ---- online softmax, warp-local (full 64-key rows in-warp)
#pragma unroll
        for (int m = 0; m < 2; m++) {
#pragma unroll
            for (int i = 0; i < 2; i++) {
                int idx = 2 * i;
                float rm = -1e30f;
#pragma unroll
                for (int ni = 0; ni < 8; ni++)
                    rm = fmaxf(rm, fmaxf(sacc[m][ni][idx], sacc[m][ni][idx + 1]));
                rm = fmaxf(rm, __shfl_xor_sync(0xffffffffu, rm, 1));
                rm = fmaxf(rm, __shfl_xor_sync(0xffffffffu, rm, 2));
                float mnew = fmaxf(mi[m][i], rm);
                float corr = __expf(mi[m][i] - mnew);
                float rs = 0.f;
#pragma unroll
                for (int ni = 0; ni < 8; ni++) {
                    float p0 = __expf(sacc[m][ni][idx]     - mnew);
                    float p1 = __expf(sacc[m][ni][idx + 1] - mnew);
                    rs += p0 + p1;
                    *(uint2*)&Ps[(wq + m * 16 + g + 8 * i) * 68 + ni * 8 + 2 * t] =
                        make_uint2(f2tf32(p0), f2tf32(p1));
                }
                rs += __shfl_xor_sync(0xffffffffu, rs, 1);
                rs += __shfl_xor_sync(0xffffffffu, rs, 2);
                li[m][i] = li[m][i] * corr + rs;
                mi[m][i] = mnew;
#pragma unroll
                for (int ni = 0; ni < 8; ni++) {
                    oacc[m][ni][idx]     *= corr;
                    oacc[m][ni][idx + 1] *= corr;
                }
            }
        }
        __syncwarp();                    // Ps writes -> PV reads (warp-private)

        // ---- O += P V : warp tile 32(q) x 64(d)
#pragma unroll
        for (int kk = 0; kk < 64; kk += 8) {
            uint32_t afr[2][4], bfr[8][2];
#pragma unroll
            for (int m = 0; m < 2; m++) {
                int rb = wq + m * 16;
                afr[m][0] = Ps[(rb + g) * 68 + kk + t];
                afr[m][1] = Ps[(rb + g + 8) * 68 + kk + t];
                afr[m][2] = Ps[(rb + g) * 68 + kk + t + 4];
                afr[m][3] = Ps[(rb + g + 8) * 68 + kk + t + 4];
            }
#pragma unroll
            for (int ni = 0; ni < 8; ni++) {
                bfr[ni][0] = Vc[(kk + t) * 72 + ni * 8 + g];
                bfr[ni][1] = Vc[(kk + t + 4) * 72 + ni * 8 + g];
            }
#pragma unroll
            for (int m = 0; m < 2; m++)
#pragma unroll
                for (int ni = 0; ni < 8; ni++)
                    mma_tf32(oacc[m][ni], afr[m], bfr[ni]);
        }
        __syncwarp();                    // PV reads -> next-iter Ps writes

        if (kt < NTOK / 64 - 1) {
            const int nxt = cur ^ 1;
            uint32_t* Kn = Ks + nxt * 64 * 68;
            uint32_t* Vn = Vs + nxt * 64 * 72;
#pragma unroll
            for (int f = 0; f < 4; f++) {
                int d = c4 * 16 + f * 4;
                *(uint4*)&Kn[j * 68 + d] = cvt4(ks[f]);
                *(uint4*)&Vn[j * 72 + d] = cvt4(vs[f]);
            }
        }
        __syncthreads();                 // protect K/V buffers across warps
    }

    // ---- epilogue: /l, write h [B,N,DIM]
#pragma unroll
    for (int m = 0; m < 2; m++) {
#pragma unroll
        for (int i = 0; i < 2; i++) {
            int idx = 2 * i;
            float invl = 1.0f / li[m][i];
            int n = q0 + wq + m * 16 + g + 8 * i;
#pragma unroll
            for (int ni = 0; ni < 8; ni++) {
                int col = ni * 8 + 2 * t;
                float2 vo;
                vo.x = oacc[m][ni][idx]     * invl;
                vo.y = oacc[m][ni][idx + 1] * invl;
                *(float2*)&g_h[(b * NTOK + n) * DIM + hh * HD + col] = vo;
            }
        }
    }
}

// ===========================================================================
// Kernel 3: gating -> scalar g per token (fp32, one warp per token).
// ===========================================================================
__global__ __launch_bounds__(256) void gate_kernel(
    const float* __restrict__ Wr, const float* __restrict__ br,
    const float* __restrict__ Ws, const float* __restrict__ bs)
{
    const int warp = threadIdx.x >> 5, lane = threadIdx.x & 31;
    const int tok = blockIdx.x * 8 + warp;
    const float* hrow = g_h + tok * DIM;

    float hv[32];
#pragma unroll
    for (int kk = 0; kk < 32; kk++) hv[kk] = hrow[lane + 32 * kk];

    float myLogit = -1e30f;
#pragma unroll
    for (int wi = 0; wi < 17; wi++) {
        const float* wrow = (wi < 15) ? (Wr + wi * DIM) : (Ws + (wi - 15) * DIM);
        float sum = 0.f;
#pragma unroll
        for (int kk = 0; kk < 32; kk++) sum += hv[kk] * wrow[lane + 32 * kk];
#pragma unroll
        for (int off = 16; off; off >>= 1) sum += __shfl_xor_sync(0xffffffffu, sum, off);
        float bias = (wi < 15) ? br[wi] : bs[wi - 15];
        if (lane == wi) myLogit = sum + bias;
    }

    float v15 = (lane < 15) ? myLogit : -1e30f;
    float m15 = v15;
#pragma unroll
    for (int off = 16; off; off >>= 1) m15 = fmaxf(m15, __shfl_xor_sync(0xffffffffu, m15, off));
    float e = (lane < 15) ? __expf(myLogit - m15) : 0.f;
    float ssum = e;
#pragma unroll
    for (int off = 16; off; off >>= 1) ssum += __shfl_xor_sync(0xffffffffu, ssum, off);
    float inv = 1.f / ssum;

    float vv = e;
    float gsum3 = 0.f;
    for (int pick = 0; pick < 3; pick++) {
        float pm = vv;
#pragma unroll
        for (int off = 16; off; off >>= 1) pm = fmaxf(pm, __shfl_xor_sync(0xffffffffu, pm, off));
        gsum3 += pm;
        unsigned eqm = __ballot_sync(0xffffffffu, vv == pm);
        int first = __ffs(eqm) - 1;
        if (lane == first) vv = -1.f;
    }
    gsum3 *= inv;

    float l15 = __shfl_sync(0xffffffffu, myLogit, 15);
    float l16 = __shfl_sync(0xffffffffu, myLogit, 16);
    float m2 = fmaxf(l15, l16);
    float e0 = __expf(l15 - m2), e1 = __expf(l16 - m2);
    float s2 = e0 + e1;
    float s0 = e0 / s2, s1 = e1 / s2;

    if (lane == 0)
        g_gate[tok] = 2.f * s0 * (s0 + s1) + 6.f * s1 * gsum3;
}

// ===========================================================================
// Kernel 4: output projection (tf32, pipelined).  out = (g .* h) @ Wp^T + bp
// grid = (32, 8), 128 threads, warp tile 64x64.
// ===========================================================================
__global__ __launch_bounds__(128) void proj_gemm(
    const float* __restrict__ Wp, const float* __restrict__ bp,
    float* __restrict__ out)
{
    __shared__ uint32_t As[2][128][20];
    __shared__ uint32_t Bs[2][128][20];

    const int tid  = threadIdx.x;
    const int warp = tid >> 5, lane = tid & 31;
    const int g = lane >> 2, t = lane & 3;
    const int wm = (warp >> 1) * 64;
    const int wn = (warp & 1) * 64;

    const int m0 = blockIdx.x * 128;
    const int n0 = blockIdx.y * 128;
    const int row = tid;

    float acc[4][8][4];
#pragma unroll
    for (int i = 0; i < 4; i++)
#pragma unroll
        for (int j = 0; j < 8; j++)
#pragma unroll
            for (int r = 0; r < 4; r++) acc[i][j][r] = 0.f;

    const float gr = g_gate[m0 + row];
    const float* aPtr = g_h + (m0 + row) * DIM;
    const float* bPtr = Wp + (n0 + row) * DIM;

    float4 sa[4], sb[4];
#pragma unroll
    for (int f = 0; f < 4; f++) {
        sa[f] = *(const float4*)(aPtr + f * 4);
        sb[f] = *(const float4*)(bPtr + f * 4);
    }
#pragma unroll
    for (int f = 0; f < 4; f++) {
        float4 ag = make_float4(sa[f].x * gr, sa[f].y * gr, sa[f].z * gr, sa[f].w * gr);
        *(uint4*)&As[0][row][f * 4] = cvt4(ag);
        *(uint4*)&Bs[0][row][f * 4] = cvt4(sb[f]);
    }
    __syncthreads();

    for (int kt = 0; kt < 64; kt++) {
        const int cur = kt & 1;
        if (kt < 63) {
            const float* ap = aPtr + (kt + 1) * 16;
            const float* bp2 = bPtr + (kt + 1) * 16;
#pragma unroll
            for (int f = 0; f < 4; f++) {
                sa[f] = *(const float4*)(ap + f * 4);
                sb[f] = *(const float4*)(bp2 + f * 4);
            }
        }

#pragma unroll
        for (int kk = 0; kk < 16; kk += 8) {
            uint32_t afr[4][4], bfr[8][2];
#pragma unroll
            for (int mi = 0; mi < 4; mi++) {
                int rb = wm + mi * 16;
                afr[mi][0] = As[cur][rb + g][kk + t];
                afr[mi][1] = As[cur][rb + g + 8][kk + t];
                afr[mi][2] = As[cur][rb + g][kk + t + 4];
                afr[mi][3] = As[cur][rb + g + 8][kk + t + 4];
            }
#pragma unroll
            for (int ni = 0; ni < 8; ni++) {
                int nb = wn + ni * 8;
                bfr[ni][0] = Bs[cur][nb + g][kk + t];
                bfr[ni][1] = Bs[cur][nb + g][kk + t + 4];
            }
#pragma unroll
            for (int mi = 0; mi < 4; mi++)
#pragma unroll
                for (int ni = 0; ni < 8; ni++)
                    mma_tf32(acc[mi][ni], afr[mi], bfr[ni]);
        }

        if (kt < 63) {
            const int nxt = cur ^ 1;
#pragma unroll
            for (int f = 0; f < 4; f++) {
                float4 ag = make_float4(sa[f].x * gr, sa[f].y * gr, sa[f].z * gr, sa[f].w * gr);
                *(uint4*)&As[nxt][row][f * 4] = cvt4(ag);
                *(uint4*)&Bs[nxt][row][f * 4] = cvt4(sb[f]);
            }
        }
        __syncthreads();
    }

#pragma unroll
    for (int mi = 0; mi < 4; mi++) {
#pragma unroll
        for (int h = 0; h < 2; h++) {
            int m = m0 + wm + mi * 16 + g + 8 * h;
#pragma unroll
            for (int ni = 0; ni < 8; ni++) {
                int col = n0 + wn + ni * 8 + 2 * t;
                float2 vo;
                vo.x = acc[mi][ni][2 * h + 0] + bp[col + 0];
                vo.y = acc[mi][ni][2 * h + 1] + bp[col + 1];
                *(float2*)&out[m * DIM + col] = vo;
            }
        }
    }
}

// ===========================================================================
extern "C" void kernel_launch(void* const* d_in, const int* in_sizes, int n_in,
                              void* d_out, int out_size)
{
    const float* x  = (const float*)d_in[0];
    const float* Wq = (const float*)d_in[1];
    const float* bq = (const float*)d_in[2];
    const float* Wk = (const float*)d_in[3];
    const float* bk = (const float*)d_in[4];
    const float* Wv = (const float*)d_in[5];
    const float* bv = (const float*)d_in[6];
    const float* Wp = (const float*)d_in[7];
    const float* bp = (const float*)d_in[8];
    const float* Wr = (const float*)d_in[9];
    const float* br = (const float*)d_in[10];
    const float* Ws = (const float*)d_in[11];
    const float* bs = (const float*)d_in[12];
    const float* tp = (const float*)d_in[13];
    const float* qe = (const float*)d_in[14];
    float* out = (float*)d_out;

    cudaFuncSetAttribute(attn_kernel,
                         cudaFuncAttributeMaxDynamicSharedMemorySize, ATTN_SMEM);

    qkv_gemm<<<dim3(32, 24), 128>>>(x, Wq, bq, Wk, bk, Wv, bv);
    attn_kernel<<<dim3(8, 32), 256, ATTN_SMEM>>>(tp, qe);
    gate_kernel<<<512, 256>>>(Wr, br, Ws, bs);
    proj_gemm<<<dim3(32, 8), 128>>>(Wp, bp, out);
}

// round 12
// speedup vs baseline: 2.9966x; 1.1943x over previous
#include <cuda_runtime.h>
#include <math.h>
#include <stdint.h>

#define B_SZ   2
#define NTOK   2048
#define DIM    1024
#define NH     16
#define HD     64
#define M_TOT  (B_SZ * NTOK)      // 4096
#define QT     256                // attention query tile

// ---------------- scratch (device globals; no runtime allocation) ----------
__device__ float g_q[B_SZ * NH * NTOK * HD];   // [B,H,N,hd]
__device__ float g_k[B_SZ * NH * NTOK * HD];
__device__ float g_v[B_SZ * NH * NTOK * HD];
__device__ float g_h[M_TOT * DIM];             // attention output [B,N,DIM]
__device__ float g_gate[M_TOT];                // per-token gate scalar

// ---------------- tf32 helpers --------------------------------------------
__device__ __forceinline__ uint32_t f2tf32(float x) {
    uint32_t r;
    asm("cvt.rna.tf32.f32 %0, %1;" : "=r"(r) : "f"(x));
    return r;
}
__device__ __forceinline__ uint4 cvt4(float4 v) {
    return make_uint4(f2tf32(v.x), f2tf32(v.y), f2tf32(v.z), f2tf32(v.w));
}

// D(16x8) += A(16x8,row) * B(8x8,col);  tf32 in, f32 accum
// A regs: a0=(g,t) a1=(g+8,t) a2=(g,t+4) a3=(g+8,t+4)
// B regs: b0=(k=t,n=g) b1=(k=t+4,n=g)
// C regs: c0=(g,2t) c1=(g,2t+1) c2=(g+8,2t) c3=(g+8,2t+1)
__device__ __forceinline__ void mma_tf32(float* c, const uint32_t* a, const uint32_t* b) {
    asm volatile(
        "mma.sync.aligned.m16n8k8.row.col.f32.tf32.tf32.f32 "
        "{%0,%1,%2,%3}, {%4,%5,%6,%7}, {%8,%9}, {%0,%1,%2,%3};"
        : "+f"(c[0]), "+f"(c[1]), "+f"(c[2]), "+f"(c[3])
        : "r"(a[0]), "r"(a[1]), "r"(a[2]), "r"(a[3]), "r"(b[0]), "r"(b[1]));
}

__device__ __forceinline__ void cp_async16(uint32_t smem_addr, const void* gptr) {
    asm volatile("cp.async.cg.shared.global [%0], [%1], 16;"
                 :: "r"(smem_addr), "l"(gptr));
}
__device__ __forceinline__ void cp_commit() {
    asm volatile("cp.async.commit_group;");
}
__device__ __forceinline__ void cp_wait0() {
    asm volatile("cp.async.wait_group 0;");
}

// ===========================================================================
// Kernel 1: fused QKV projection (tf32, cp.async 2-stage pipeline).
// Block 128x128, 8 warps (warp tile 64x32), K-step 16, 64 iterations.
// f32 tiles in smem; cvt.rna at fragment load.  grid = (32, 24), 256 thr.
// ===========================================================================
__global__ __launch_bounds__(256, 2) void qkv_gemm(
    const float* __restrict__ x,
    const float* __restrict__ Wq, const float* __restrict__ bq,
    const float* __restrict__ Wk, const float* __restrict__ bk,
    const float* __restrict__ Wv, const float* __restrict__ bv)
{
    __shared__ float As[2][128][20];
    __shared__ float Bs[2][128][20];

    const int tid  = threadIdx.x;
    const int warp = tid >> 5, lane = tid & 31;
    const int g = lane >> 2, t = lane & 3;
    const int wm = (warp >> 2) * 64;        // 0 or 64
    const int wn = (warp & 3) * 32;         // 0,32,64,96

    const int m0 = blockIdx.x * 128;
    const int n0 = blockIdx.y * 128;
    const int seg = n0 >> 10;
    const float* W    = (seg == 0) ? Wq : (seg == 1) ? Wk : Wv;
    const float* bias = (seg == 0) ? bq : (seg == 1) ? bk : bv;
    float* outp       = (seg == 0) ? g_q : (seg == 1) ? g_k : g_v;
    const int ncol0 = n0 & 1023;

    const int row = tid >> 1;               // 0..127
    const int q8  = (tid & 1) * 8;          // 0 or 8

    float acc[4][4][4];
#pragma unroll
    for (int i = 0; i < 4; i++)
#pragma unroll
        for (int j = 0; j < 4; j++)
#pragma unroll
            for (int r = 0; r < 4; r++) acc[i][j][r] = 0.f;

    const float* aPtr = x + (m0 + row) * DIM + q8;
    const float* bPtr = W + (ncol0 + row) * DIM + q8;
    const uint32_t sA0 = (uint32_t)__cvta_generic_to_shared(&As[0][row][q8]);
    const uint32_t sB0 = (uint32_t)__cvta_generic_to_shared(&Bs[0][row][q8]);
    const uint32_t stageBytes = 128 * 20 * 4;

    // prologue: stage 0
    cp_async16(sA0,      aPtr);
    cp_async16(sA0 + 16, aPtr + 4);
    cp_async16(sB0,      bPtr);
    cp_async16(sB0 + 16, bPtr + 4);
    cp_commit();

    for (int kt = 0; kt < 64; kt++) {
        const int cur = kt & 1;
        cp_wait0();
        __syncthreads();
        if (kt < 63) {
            const uint32_t off = (cur ^ 1) * stageBytes;
            const float* ap = aPtr + (kt + 1) * 16;
            const float* bp = bPtr + (kt + 1) * 16;
            cp_async16(sA0 + off,      ap);
            cp_async16(sA0 + off + 16, ap + 4);
            cp_async16(sB0 + off,      bp);
            cp_async16(sB0 + off + 16, bp + 4);
            cp_commit();
        }

#pragma unroll
        for (int kk = 0; kk < 16; kk += 8) {
            uint32_t afr[4][4], bfr[4][2];
#pragma unroll
            for (int mi = 0; mi < 4; mi++) {
                int rb = wm + mi * 16;
                afr[mi][0] = f2tf32(As[cur][rb + g][kk + t]);
                afr[mi][1] = f2tf32(As[cur][rb + g + 8][kk + t]);
                afr[mi][2] = f2tf32(As[cur][rb + g][kk + t + 4]);
                afr[mi][3] = f2tf32(As[cur][rb + g + 8][kk + t + 4]);
            }
#pragma unroll
            for (int ni = 0; ni < 4; ni++) {
                int nb = wn + ni * 8;
                bfr[ni][0] = f2tf32(Bs[cur][nb + g][kk + t]);
                bfr[ni][1] = f2tf32(Bs[cur][nb + g][kk + t + 4]);
            }
#pragma unroll
            for (int mi = 0; mi < 4; mi++)
#pragma unroll
                for (int ni = 0; ni < 4; ni++)
                    mma_tf32(acc[mi][ni], afr[mi], bfr[ni]);
        }
    }

    // epilogue: bias + scatter to [B,H,N,hd]
#pragma unroll
    for (int mi = 0; mi < 4; mi++) {
#pragma unroll
        for (int h = 0; h < 2; h++) {
            int m = m0 + wm + mi * 16 + g + 8 * h;
            int bb = m >> 11, n = m & 2047;
#pragma unroll
            for (int ni = 0; ni < 4; ni++) {
                int col = ncol0 + wn + ni * 8 + 2 * t;
                int head = col >> 6, d = col & 63;
                float2 vo;
                vo.x = acc[mi][ni][2 * h + 0] + bias[col + 0];
                vo.y = acc[mi][ni][2 * h + 1] + bias[col + 1];
                *(float2*)&outp[(((bb * NH + head) * NTOK) + n) * HD + d] = vo;
            }
        }
    }
}

// ===========================================================================
// Kernel 2: flash attention, tf32 mma, pipelined K/V double buffer.
// Q-tile 256, key-tile 64.  8 warps x 32 query rows; each warp owns all 64
// keys for its rows (warp-local online softmax).
// grid = (NTOK/256 = 8, B*H = 32), 256 threads, ~206KB dynamic smem.
// ===========================================================================
#define ATTN_SMEM ((QT * 68 * 2 + 2 * 64 * 68 + 2 * 64 * 72) * 4)

__global__ __launch_bounds__(256, 1) void attn_kernel(
    const float* __restrict__ temperature,
    const float* __restrict__ qe)
{
    extern __shared__ uint32_t smu[];
    uint32_t* Qs = smu;                       // [q][d]   stride 68, QT rows
    uint32_t* Ks = Qs + QT * 68;              // [2][key][d] stride 68
    uint32_t* Vs = Ks + 2 * 64 * 68;          // [2][key][d] stride 72
    uint32_t* Ps = Vs + 2 * 64 * 72;          // [q][key] stride 68, QT rows

    const int tid  = threadIdx.x;
    const int warp = tid >> 5, lane = tid & 31;
    const int g = lane >> 2, t = lane & 3;
    const int wq = warp * 32;                 // this warp's query-row base

    const int bh = blockIdx.y;
    const int b = bh >> 4, hh = bh & 15;
    const int q0 = blockIdx.x * QT;

    const float* qbase = g_q + (bh * NTOK + q0) * HD;
    const float* kbase = g_k + (long)bh * NTOK * HD;
    const float* vbase = g_v + (long)bh * NTOK * HD;

    // ---- Q preprocess: one full row per thread (r = tid, 0..255)
    {
        int r = tid;
        float qv[64];
        float ss = 0.f;
#pragma unroll
        for (int f = 0; f < 16; f++) {
            float4 v = *(const float4*)(qbase + r * HD + f * 4);
            qv[f * 4 + 0] = v.x; qv[f * 4 + 1] = v.y;
            qv[f * 4 + 2] = v.z; qv[f * 4 + 3] = v.w;
            ss += v.x * v.x + v.y * v.y + v.z * v.z + v.w * v.w;
        }
        float inv = rsqrtf(ss);
        float tt = temperature[hh];
        float sp = (tt > 20.f) ? tt : log1pf(__expf(tt));
        float tc = sp * 0.125f;                      // /sqrt(64)
        const float* qeh = qe + hh * HD;
#pragma unroll
        for (int f = 0; f < 16; f++) {
            uint4 u;
            u.x = f2tf32((qv[f * 4 + 0] * inv + qeh[f * 4 + 0]) * tc);
            u.y = f2tf32((qv[f * 4 + 1] * inv + qeh[f * 4 + 1]) * tc);
            u.z = f2tf32((qv[f * 4 + 2] * inv + qeh[f * 4 + 2]) * tc);
            u.w = f2tf32((qv[f * 4 + 3] * inv + qeh[f * 4 + 3]) * tc);
            *(uint4*)&Qs[r * 68 + f * 4] = u;
        }
    }

    // ---- K/V staging: thread (j = tid>>2, c4 = tid&3) loads 4 float4 each
    const int j  = tid >> 2;
    const int c4 = tid & 3;
    float4 ks[4], vs[4];
    {
        const float* kp = kbase + j * HD + c4 * 16;
        const float* vp = vbase + j * HD + c4 * 16;
#pragma unroll
        for (int f = 0; f < 4; f++) {
            ks[f] = *(const float4*)(kp + f * 4);
            vs[f] = *(const float4*)(vp + f * 4);
        }
    }
#pragma unroll
    for (int f = 0; f < 4; f++) {
        int d = c4 * 16 + f * 4;
        *(uint4*)&Ks[j * 68 + d] = cvt4(ks[f]);
        *(uint4*)&Vs[j * 72 + d] = cvt4(vs[f]);
    }
    __syncthreads();

    float oacc[2][8][4];                 // [m-tile][d-block][reg]
    float mi[2][2], li[2][2];            // [m-tile][row-half]
#pragma unroll
    for (int m = 0; m < 2; m++) {
#pragma unroll
        for (int i = 0; i < 8; i++)
#pragma unroll
            for (int r = 0; r < 4; r++) oacc[m][i][r] = 0.f;
        mi[m][0] = mi[m][1] = -1e30f;
        li[m][0] = li[m][1] = 0.f;
    }

    for (int kt = 0; kt < NTOK / 64; kt++) {
        const int cur = kt & 1;
        uint32_t* Kc = Ks + cur * 64 * 68;
        uint32_t* Vc = Vs + cur * 64 * 72;

        if (kt < NTOK / 64 - 1) {
            const float* kp = kbase + ((kt + 1) * 64 + j) * HD + c4 * 16;
            const float* vp = vbase + ((kt + 1) * 64 + j) * HD + c4 * 16;
#pragma unroll
            for (int f = 0; f < 4; f++) {
                ks[f] = *(const float4*)(kp + f * 4);
                vs[f] = *(const float4*)(vp + f * 4);
            }
        }

        // ---- S = Q K^T : warp tile 32(q) x 64(key)
        float sacc[2][8][4];
#pragma unroll
        for (int m = 0; m < 2; m++)
#pragma unroll
            for (int i = 0; i < 8; i++)
#pragma unroll
                for (int r = 0; r < 4; r++) sacc[m][i][r] = 0.f;

#pragma unroll
        for (int kk = 0; kk < 64; kk += 8) {
            uint32_t afr[2][4], bfr[8][2];
#pragma unroll
            for (int m = 0; m < 2; m++) {
                int rb = wq + m * 16;
                afr[m][0] = Qs[(rb + g) * 68 + kk + t];
                afr[m][1] = Qs[(rb + g + 8) * 68 + kk + t];
                afr[m][2] = Qs[(rb + g) * 68 + kk + t + 4];
                afr[m][3] = Qs[(rb + g + 8) * 68 + kk + t + 4];
            }
#pragma unroll
            for (int ni = 0; ni < 8; ni++) {
                bfr[ni][0] = Kc[(ni * 8 + g) * 68 + kk + t];
                bfr[ni][1] = Kc[(ni * 8 + g) * 68 + kk + t + 4];
            }
#pragma unroll
            for (int m = 0; m < 2; m++)
#pragma unroll
                for (int ni = 0; ni < 8; ni++)
                    mma_tf32(sacc[m][ni], afr[m], bfr[ni]);
        }

        // ---- online softmax, warp-local (full 64-key rows in-warp)
#pragma unroll
        for (int m = 0; m < 2; m++) {
#pragma unroll
            for (int i = 0; i < 2; i++) {
                int idx = 2 * i;
                float rm = -1e30f;
#pragma unroll
                for (int ni = 0; ni < 8; ni++)
                    rm = fmaxf(rm, fmaxf(sacc[m][ni][idx], sacc[m][ni][idx + 1]));
                rm = fmaxf(rm, __shfl_xor_sync(0xffffffffu, rm, 1));
                rm = fmaxf(rm, __shfl_xor_sync(0xffffffffu, rm, 2));
                float mnew = fmaxf(mi[m][i], rm);
                float corr = __expf(mi[m][i] - mnew);
                float rs = 0.f;
#pragma unroll
                for (int ni = 0; ni < 8; ni++) {
                    float p0 = __expf(sacc[m][ni][idx]     - mnew);
                    float p1 = __expf(sacc[m][ni][idx + 1] - mnew);
                    rs += p0 + p1;
                    *(uint2*)&Ps[(wq + m * 16 + g + 8 * i) * 68 + ni * 8 + 2 * t] =
                        make_uint2(f2tf32(p0), f2tf32(p1));
                }
                rs += __shfl_xor_sync(0xffffffffu, rs, 1);
                rs += __shfl_xor_sync(0xffffffffu, rs, 2);
                li[m][i] = li[m][i] * corr + rs;
                mi[m][i] = mnew;
#pragma unroll
                for (int ni = 0; ni < 8; ni++) {
                    oacc[m][ni][idx]     *= corr;
                    oacc[m][ni][idx + 1] *= corr;
                }
            }
        }
        __syncwarp();                    // Ps writes -> PV reads (warp-private)

        // ---- O += P V : warp tile 32(q) x 64(d)
#pragma unroll
        for (int kk = 0; kk < 64; kk += 8) {
            uint32_t afr[2][4], bfr[8][2];
#pragma unroll
            for (int m = 0; m < 2; m++) {
                int rb = wq + m * 16;
                afr[m][0] = Ps[(rb + g) * 68 + kk + t];
                afr[m][1] = Ps[(rb + g + 8) * 68 + kk + t];
                afr[m][2] = Ps[(rb + g) * 68 + kk + t + 4];
                afr[m][3] = Ps[(rb + g + 8) * 68 + kk + t + 4];
            }
#pragma unroll
            for (int ni = 0; ni < 8; ni++) {
                bfr[ni][0] = Vc[(kk + t) * 72 + ni * 8 + g];
                bfr[ni][1] = Vc[(kk + t + 4) * 72 + ni * 8 + g];
            }
#pragma unroll
            for (int m = 0; m < 2; m++)
#pragma unroll
                for (int ni = 0; ni < 8; ni++)
                    mma_tf32(oacc[m][ni], afr[m], bfr[ni]);
        }
        __syncwarp();                    // PV reads -> next-iter Ps writes

        if (kt < NTOK / 64 - 1) {
            const int nxt = cur ^ 1;
            uint32_t* Kn = Ks + nxt * 64 * 68;
            uint32_t* Vn = Vs + nxt * 64 * 72;
#pragma unroll
            for (int f = 0; f < 4; f++) {
                int d = c4 * 16 + f * 4;
                *(uint4*)&Kn[j * 68 + d] = cvt4(ks[f]);
                *(uint4*)&Vn[j * 72 + d] = cvt4(vs[f]);
            }
        }
        __syncthreads();                 // protect K/V buffers across warps
    }

    // ---- epilogue: /l, write h [B,N,DIM]
#pragma unroll
    for (int m = 0; m < 2; m++) {
#pragma unroll
        for (int i = 0; i < 2; i++) {
            int idx = 2 * i;
            float invl = 1.0f / li[m][i];
            int n = q0 + wq + m * 16 + g + 8 * i;
#pragma unroll
            for (int ni = 0; ni < 8; ni++) {
                int col = ni * 8 + 2 * t;
                float2 vo;
                vo.x = oacc[m][ni][idx]     * invl;
                vo.y = oacc[m][ni][idx + 1] * invl;
                *(float2*)&g_h[(b * NTOK + n) * DIM + hh * HD + col] = vo;
            }
        }
    }
}

// ===========================================================================
// Kernel 3: gating -> scalar g per token (fp32, one warp per token).
// ===========================================================================
__global__ __launch_bounds__(256) void gate_kernel(
    const float* __restrict__ Wr, const float* __restrict__ br,
    const float* __restrict__ Ws, const float* __restrict__ bs)
{
    const int warp = threadIdx.x >> 5, lane = threadIdx.x & 31;
    const int tok = blockIdx.x * 8 + warp;
    const float* hrow = g_h + tok * DIM;

    float hv[32];
#pragma unroll
    for (int kk = 0; kk < 32; kk++) hv[kk] = hrow[lane + 32 * kk];

    float myLogit = -1e30f;
#pragma unroll
    for (int wi = 0; wi < 17; wi++) {
        const float* wrow = (wi < 15) ? (Wr + wi * DIM) : (Ws + (wi - 15) * DIM);
        float sum = 0.f;
#pragma unroll
        for (int kk = 0; kk < 32; kk++) sum += hv[kk] * wrow[lane + 32 * kk];
#pragma unroll
        for (int off = 16; off; off >>= 1) sum += __shfl_xor_sync(0xffffffffu, sum, off);
        float bias = (wi < 15) ? br[wi] : bs[wi - 15];
        if (lane == wi) myLogit = sum + bias;
    }

    float v15 = (lane < 15) ? myLogit : -1e30f;
    float m15 = v15;
#pragma unroll
    for (int off = 16; off; off >>= 1) m15 = fmaxf(m15, __shfl_xor_sync(0xffffffffu, m15, off));
    float e = (lane < 15) ? __expf(myLogit - m15) : 0.f;
    float ssum = e;
#pragma unroll
    for (int off = 16; off; off >>= 1) ssum += __shfl_xor_sync(0xffffffffu, ssum, off);
    float inv = 1.f / ssum;

    float vv = e;
    float gsum3 = 0.f;
    for (int pick = 0; pick < 3; pick++) {
        float pm = vv;
#pragma unroll
        for (int off = 16; off; off >>= 1) pm = fmaxf(pm, __shfl_xor_sync(0xffffffffu, pm, off));
        gsum3 += pm;
        unsigned eqm = __ballot_sync(0xffffffffu, vv == pm);
        int first = __ffs(eqm) - 1;
        if (lane == first) vv = -1.f;
    }
    gsum3 *= inv;

    float l15 = __shfl_sync(0xffffffffu, myLogit, 15);
    float l16 = __shfl_sync(0xffffffffu, myLogit, 16);
    float m2 = fmaxf(l15, l16);
    float e0 = __expf(l15 - m2), e1 = __expf(l16 - m2);
    float s2 = e0 + e1;
    float s0 = e0 / s2, s1 = e1 / s2;

    if (lane == 0)
        g_gate[tok] = 2.f * s0 * (s0 + s1) + 6.f * s1 * gsum3;
}

// ===========================================================================
// Kernel 4: output projection (tf32, cp.async pipeline).
// out = g .* (h @ Wp^T) + bp   (gate commutes with row-scalar multiply,
// applied in the epilogue).  grid = (32, 8), 256 threads.
// ===========================================================================
__global__ __launch_bounds__(256, 2) void proj_gemm(
    const float* __restrict__ Wp, const float* __restrict__ bp,
    float* __restrict__ out)
{
    __shared__ float As[2][128][20];
    __shared__ float Bs[2][128][20];

    const int tid  = threadIdx.x;
    const int warp = tid >> 5, lane = tid & 31;
    const int g = lane >> 2, t = lane & 3;
    const int wm = (warp >> 2) * 64;
    const int wn = (warp & 3) * 32;

    const int m0 = blockIdx.x * 128;
    const int n0 = blockIdx.y * 128;
    const int row = tid >> 1;
    const int q8  = (tid & 1) * 8;

    float acc[4][4][4];
#pragma unroll
    for (int i = 0; i < 4; i++)
#pragma unroll
        for (int j = 0; j < 4; j++)
#pragma unroll
            for (int r = 0; r < 4; r++) acc[i][j][r] = 0.f;

    const float* aPtr = g_h + (m0 + row) * DIM + q8;
    const float* bPtr = Wp + (n0 + row) * DIM + q8;
    const uint32_t sA0 = (uint32_t)__cvta_generic_to_shared(&As[0][row][q8]);
    const uint32_t sB0 = (uint32_t)__cvta_generic_to_shared(&Bs[0][row][q8]);
    const uint32_t stageBytes = 128 * 20 * 4;

    cp_async16(sA0,      aPtr);
    cp_async16(sA0 + 16, aPtr + 4);
    cp_async16(sB0,      bPtr);
    cp_async16(sB0 + 16, bPtr + 4);
    cp_commit();

    for (int kt = 0; kt < 64; kt++) {
        const int cur = kt & 1;
        cp_wait0();
        __syncthreads();
        if (kt < 63) {
            const uint32_t off = (cur ^ 1) * stageBytes;
            const float* ap = aPtr + (kt + 1) * 16;
            const float* bp2 = bPtr + (kt + 1) * 16;
            cp_async16(sA0 + off,      ap);
            cp_async16(sA0 + off + 16, ap + 4);
            cp_async16(sB0 + off,      bp2);
            cp_async16(sB0 + off + 16, bp2 + 4);
            cp_commit();
        }

#pragma unroll
        for (int kk = 0; kk < 16; kk += 8) {
            uint32_t afr[4][4], bfr[4][2];
#pragma unroll
            for (int mi = 0; mi < 4; mi++) {
                int rb = wm + mi * 16;
                afr[mi][0] = f2tf32(As[cur][rb + g][kk + t]);
                afr[mi][1] = f2tf32(As[cur][rb + g + 8][kk + t]);
                afr[mi][2] = f2tf32(As[cur][rb + g][kk + t + 4]);
                afr[mi][3] = f2tf32(As[cur][rb + g + 8][kk + t + 4]);
            }
#pragma unroll
            for (int ni = 0; ni < 4; ni++) {
                int nb = wn + ni * 8;
                bfr[ni][0] = f2tf32(Bs[cur][nb + g][kk + t]);
                bfr[ni][1] = f2tf32(Bs[cur][nb + g][kk + t + 4]);
            }
#pragma unroll
            for (int mi = 0; mi < 4; mi++)
#pragma unroll
                for (int ni = 0; ni < 4; ni++)
                    mma_tf32(acc[mi][ni], afr[mi], bfr[ni]);
        }
    }

    // epilogue: apply row gate, add bias
#pragma unroll
    for (int mi = 0; mi < 4; mi++) {
#pragma unroll
        for (int h = 0; h < 2; h++) {
            int m = m0 + wm + mi * 16 + g + 8 * h;
            float gm = g_gate[m];
#pragma unroll
            for (int ni = 0; ni < 4; ni++) {
                int col = n0 + wn + ni * 8 + 2 * t;
                float2 vo;
                vo.x = gm * acc[mi][ni][2 * h + 0] + bp[col + 0];
                vo.y = gm * acc[mi][ni][2 * h + 1] + bp[col + 1];
                *(float2*)&out[m * DIM + col] = vo;
            }
        }
    }
}

// ===========================================================================
extern "C" void kernel_launch(void* const* d_in, const int* in_sizes, int n_in,
                              void* d_out, int out_size)
{
    const float* x  = (const float*)d_in[0];
    const float* Wq = (const float*)d_in[1];
    const float* bq = (const float*)d_in[2];
    const float* Wk = (const float*)d_in[3];
    const float* bk = (const float*)d_in[4];
    const float* Wv = (const float*)d_in[5];
    const float* bv = (const float*)d_in[6];
    const float* Wp = (const float*)d_in[7];
    const float* bp = (const float*)d_in[8];
    const float* Wr = (const float*)d_in[9];
    const float* br = (const float*)d_in[10];
    const float* Ws = (const float*)d_in[11];
    const float* bs = (const float*)d_in[12];
    const float* tp = (const float*)d_in[13];
    const float* qe = (const float*)d_in[14];
    float* out = (float*)d_out;

    cudaFuncSetAttribute(attn_kernel,
                         cudaFuncAttributeMaxDynamicSharedMemorySize, ATTN_SMEM);

    qkv_gemm<<<dim3(32, 24), 256>>>(x, Wq, bq, Wk, bk, Wv, bv);
    attn_kernel<<<dim3(8, 32), 256, ATTN_SMEM>>>(tp, qe);
    gate_kernel<<<512, 256>>>(Wr, br, Ws, bs);
    proj_gemm<<<dim3(32, 8), 256>>>(Wp, bp, out);
}

// round 13
// speedup vs baseline: 3.0762x; 1.0265x over previous
#include <cuda_runtime.h>
#include <math.h>
#include <stdint.h>

#define B_SZ   2
#define NTOK   2048
#define DIM    1024
#define NH     16
#define HD     64
#define M_TOT  (B_SZ * NTOK)      // 4096
#define QT     256                // attention query tile

// ---------------- scratch (device globals; no runtime allocation) ----------
__device__ float g_x [M_TOT * DIM];            // tf32-rounded x
__device__ float g_wq[DIM * DIM];              // tf32-rounded weights
__device__ float g_wk[DIM * DIM];
__device__ float g_wv[DIM * DIM];
__device__ float g_wp[DIM * DIM];
__device__ float g_q[B_SZ * NH * NTOK * HD];   // [B,H,N,hd] (tf32-rounded)
__device__ float g_k[B_SZ * NH * NTOK * HD];
__device__ float g_v[B_SZ * NH * NTOK * HD];
__device__ float g_h[M_TOT * DIM];             // attention out (tf32-rounded)
__device__ float g_gate[M_TOT];                // per-token gate scalar

// ---------------- tf32 helpers --------------------------------------------
__device__ __forceinline__ uint32_t f2tf32(float x) {
    uint32_t r;
    asm("cvt.rna.tf32.f32 %0, %1;" : "=r"(r) : "f"(x));
    return r;
}
__device__ __forceinline__ float rnd32(float x) { return __uint_as_float(f2tf32(x)); }

// D(16x8) += A(16x8,row) * B(8x8,col);  tf32 in, f32 accum
// A regs: a0=(g,t) a1=(g+8,t) a2=(g,t+4) a3=(g+8,t+4)
// B regs: b0=(k=t,n=g) b1=(k=t+4,n=g)
// C regs: c0=(g,2t) c1=(g,2t+1) c2=(g+8,2t) c3=(g+8,2t+1)
__device__ __forceinline__ void mma_tf32(float* c, const uint32_t* a, const uint32_t* b) {
    asm volatile(
        "mma.sync.aligned.m16n8k8.row.col.f32.tf32.tf32.f32 "
        "{%0,%1,%2,%3}, {%4,%5,%6,%7}, {%8,%9}, {%0,%1,%2,%3};"
        : "+f"(c[0]), "+f"(c[1]), "+f"(c[2]), "+f"(c[3])
        : "r"(a[0]), "r"(a[1]), "r"(a[2]), "r"(a[3]), "r"(b[0]), "r"(b[1]));
}

__device__ __forceinline__ void cp_async16(uint32_t smem_addr, const void* gptr) {
    asm volatile("cp.async.cg.shared.global [%0], [%1], 16;"
                 :: "r"(smem_addr), "l"(gptr));
}
__device__ __forceinline__ void cp_commit() {
    asm volatile("cp.async.commit_group;");
}
__device__ __forceinline__ void cp_wait0() {
    asm volatile("cp.async.wait_group 0;");
}

// ===========================================================================
// Kernel 0: pre-convert fp32 -> tf32-rounded fp32 (grid-stride float4).
// ===========================================================================
__global__ void cvt_kernel(const float4* __restrict__ src, float4* __restrict__ dst, int n4)
{
    int i = blockIdx.x * blockDim.x + threadIdx.x;
    int stride = gridDim.x * blockDim.x;
    for (; i < n4; i += stride) {
        float4 v = src[i];
        dst[i] = make_float4(rnd32(v.x), rnd32(v.y), rnd32(v.z), rnd32(v.w));
    }
}

// ===========================================================================
// Kernel 1: fused QKV projection (tf32, cp.async 2-stage, cvt-free mainloop).
// Operands already tf32-rounded in gmem.  Block 128x128, 8 warps (64x32).
// grid = (32, 24), 256 threads.
// ===========================================================================
__global__ __launch_bounds__(256, 2) void qkv_gemm(
    const float* __restrict__ bq, const float* __restrict__ bk,
    const float* __restrict__ bv)
{
    __shared__ uint32_t As[2][128][20];
    __shared__ uint32_t Bs[2][128][20];

    const int tid  = threadIdx.x;
    const int warp = tid >> 5, lane = tid & 31;
    const int g = lane >> 2, t = lane & 3;
    const int wm = (warp >> 2) * 64;
    const int wn = (warp & 3) * 32;

    const int m0 = blockIdx.x * 128;
    const int n0 = blockIdx.y * 128;
    const int seg = n0 >> 10;
    const float* W    = (seg == 0) ? g_wq : (seg == 1) ? g_wk : g_wv;
    const float* bias = (seg == 0) ? bq : (seg == 1) ? bk : bv;
    float* outp       = (seg == 0) ? g_q : (seg == 1) ? g_k : g_v;
    const int ncol0 = n0 & 1023;

    const int row = tid >> 1;
    const int q8  = (tid & 1) * 8;

    float acc[4][4][4];
#pragma unroll
    for (int i = 0; i < 4; i++)
#pragma unroll
        for (int j = 0; j < 4; j++)
#pragma unroll
            for (int r = 0; r < 4; r++) acc[i][j][r] = 0.f;

    const float* aPtr = g_x + (m0 + row) * DIM + q8;
    const float* bPtr = W + (ncol0 + row) * DIM + q8;
    const uint32_t sA0 = (uint32_t)__cvta_generic_to_shared(&As[0][row][q8]);
    const uint32_t sB0 = (uint32_t)__cvta_generic_to_shared(&Bs[0][row][q8]);
    const uint32_t stageBytes = 128 * 20 * 4;

    cp_async16(sA0,      aPtr);
    cp_async16(sA0 + 16, aPtr + 4);
    cp_async16(sB0,      bPtr);
    cp_async16(sB0 + 16, bPtr + 4);
    cp_commit();

    for (int kt = 0; kt < 64; kt++) {
        const int cur = kt & 1;
        cp_wait0();
        __syncthreads();
        if (kt < 63) {
            const uint32_t off = (cur ^ 1) * stageBytes;
            const float* ap = aPtr + (kt + 1) * 16;
            const float* bp = bPtr + (kt + 1) * 16;
            cp_async16(sA0 + off,      ap);
            cp_async16(sA0 + off + 16, ap + 4);
            cp_async16(sB0 + off,      bp);
            cp_async16(sB0 + off + 16, bp + 4);
            cp_commit();
        }

#pragma unroll
        for (int kk = 0; kk < 16; kk += 8) {
            uint32_t afr[4][4], bfr[4][2];
#pragma unroll
            for (int mi = 0; mi < 4; mi++) {
                int rb = wm + mi * 16;
                afr[mi][0] = As[cur][rb + g][kk + t];
                afr[mi][1] = As[cur][rb + g + 8][kk + t];
                afr[mi][2] = As[cur][rb + g][kk + t + 4];
                afr[mi][3] = As[cur][rb + g + 8][kk + t + 4];
            }
#pragma unroll
            for (int ni = 0; ni < 4; ni++) {
                int nb = wn + ni * 8;
                bfr[ni][0] = Bs[cur][nb + g][kk + t];
                bfr[ni][1] = Bs[cur][nb + g][kk + t + 4];
            }
#pragma unroll
            for (int mi = 0; mi < 4; mi++)
#pragma unroll
                for (int ni = 0; ni < 4; ni++)
                    mma_tf32(acc[mi][ni], afr[mi], bfr[ni]);
        }
    }

    // epilogue: bias, round to tf32 (consumed by tf32 attention), scatter
#pragma unroll
    for (int mi = 0; mi < 4; mi++) {
#pragma unroll
        for (int h = 0; h < 2; h++) {
            int m = m0 + wm + mi * 16 + g + 8 * h;
            int bb = m >> 11, n = m & 2047;
#pragma unroll
            for (int ni = 0; ni < 4; ni++) {
                int col = ncol0 + wn + ni * 8 + 2 * t;
                int head = col >> 6, d = col & 63;
                float2 vo;
                vo.x = rnd32(acc[mi][ni][2 * h + 0] + bias[col + 0]);
                vo.y = rnd32(acc[mi][ni][2 * h + 1] + bias[col + 1]);
                *(float2*)&outp[(((bb * NH + head) * NTOK) + n) * HD + d] = vo;
            }
        }
    }
}

// ===========================================================================
// Kernel 2: flash attention, tf32 mma, cp.async K/V double buffer.
// Q-tile 256, key-tile 64.  8 warps x 32 query rows; each warp owns all 64
// keys for its rows (warp-local online softmax).  K/V already tf32-rounded.
// grid = (NTOK/256 = 8, B*H = 32), 256 threads, ~206KB dynamic smem.
// ===========================================================================
#define ATTN_SMEM ((QT * 68 * 2 + 2 * 64 * 68 + 2 * 64 * 72) * 4)

__global__ __launch_bounds__(256, 1) void attn_kernel(
    const float* __restrict__ temperature,
    const float* __restrict__ qe)
{
    extern __shared__ uint32_t smu[];
    uint32_t* Qs = smu;                       // [q][d]   stride 68, QT rows
    uint32_t* Ks = Qs + QT * 68;              // [2][key][d] stride 68
    uint32_t* Vs = Ks + 2 * 64 * 68;          // [2][key][d] stride 72
    uint32_t* Ps = Vs + 2 * 64 * 72;          // [q][key] stride 68, QT rows

    const int tid  = threadIdx.x;
    const int warp = tid >> 5, lane = tid & 31;
    const int g = lane >> 2, t = lane & 3;
    const int wq = warp * 32;

    const int bh = blockIdx.y;
    const int b = bh >> 4, hh = bh & 15;
    const int q0 = blockIdx.x * QT;

    const float* qbase = g_q + (bh * NTOK + q0) * HD;
    const float* kbase = g_k + (long)bh * NTOK * HD;
    const float* vbase = g_v + (long)bh * NTOK * HD;

    // ---- K/V cp.async staging geometry: row j, 4 float4 per thread
    const int j  = tid >> 2;
    const int c4 = tid & 3;
    const uint32_t sK0 = (uint32_t)__cvta_generic_to_shared(&Ks[j * 68 + c4 * 16]);
    const uint32_t sV0 = (uint32_t)__cvta_generic_to_shared(&Vs[j * 72 + c4 * 16]);
    const uint32_t kStage = 64 * 68 * 4, vStage = 64 * 72 * 4;
    const float* kp0 = kbase + j * HD + c4 * 16;
    const float* vp0 = vbase + j * HD + c4 * 16;

    // prologue: stage 0 K/V
#pragma unroll
    for (int f = 0; f < 4; f++) {
        cp_async16(sK0 + f * 16, kp0 + f * 4);
        cp_async16(sV0 + f * 16, vp0 + f * 4);
    }
    cp_commit();

    // ---- Q preprocess (overlaps the K/V load): one row per thread
    {
        int r = tid;
        float qv[64];
        float ss = 0.f;
#pragma unroll
        for (int f = 0; f < 16; f++) {
            float4 v = *(const float4*)(qbase + r * HD + f * 4);
            qv[f * 4 + 0] = v.x; qv[f * 4 + 1] = v.y;
            qv[f * 4 + 2] = v.z; qv[f * 4 + 3] = v.w;
            ss += v.x * v.x + v.y * v.y + v.z * v.z + v.w * v.w;
        }
        float inv = rsqrtf(ss);
        float tt = temperature[hh];
        float sp = (tt > 20.f) ? tt : log1pf(__expf(tt));
        float tc = sp * 0.125f;                      // /sqrt(64)
        const float* qeh = qe + hh * HD;
#pragma unroll
        for (int f = 0; f < 16; f++) {
            uint4 u;
            u.x = f2tf32((qv[f * 4 + 0] * inv + qeh[f * 4 + 0]) * tc);
            u.y = f2tf32((qv[f * 4 + 1] * inv + qeh[f * 4 + 1]) * tc);
            u.z = f2tf32((qv[f * 4 + 2] * inv + qeh[f * 4 + 2]) * tc);
            u.w = f2tf32((qv[f * 4 + 3] * inv + qeh[f * 4 + 3]) * tc);
            *(uint4*)&Qs[r * 68 + f * 4] = u;
        }
    }

    float oacc[2][8][4];
    float mi[2][2], li[2][2];
#pragma unroll
    for (int m = 0; m < 2; m++) {
#pragma unroll
        for (int i = 0; i < 8; i++)
#pragma unroll
            for (int r = 0; r < 4; r++) oacc[m][i][r] = 0.f;
        mi[m][0] = mi[m][1] = -1e30f;
        li[m][0] = li[m][1] = 0.f;
    }

    for (int kt = 0; kt < NTOK / 64; kt++) {
        const int cur = kt & 1;
        uint32_t* Kc = Ks + cur * 64 * 68;
        uint32_t* Vc = Vs + cur * 64 * 72;

        cp_wait0();
        __syncthreads();                 // cur tile visible; prev compute done

        if (kt < NTOK / 64 - 1) {
            const uint32_t off = (cur ^ 1) ? 0 : 1;   // next stage index
            const uint32_t kOff = (cur ^ 1) * kStage;
            const uint32_t vOff = (cur ^ 1) * vStage;
            const float* kp = kp0 + (kt + 1) * 64 * HD;
            const float* vp = vp0 + (kt + 1) * 64 * HD;
            (void)off;
#pragma unroll
            for (int f = 0; f < 4; f++) {
                cp_async16(sK0 + kOff + f * 16, kp + f * 4);
                cp_async16(sV0 + vOff + f * 16, vp + f * 4);
            }
            cp_commit();
        }

        // ---- S = Q K^T : warp tile 32(q) x 64(key)
        float sacc[2][8][4];
#pragma unroll
        for (int m = 0; m < 2; m++)
#pragma unroll
            for (int i = 0; i < 8; i++)
#pragma unroll
                for (int r = 0; r < 4; r++) sacc[m][i][r] = 0.f;

#pragma unroll
        for (int kk = 0; kk < 64; kk += 8) {
            uint32_t afr[2][4], bfr[8][2];
#pragma unroll
            for (int m = 0; m < 2; m++) {
                int rb = wq + m * 16;
                afr[m][0] = Qs[(rb + g) * 68 + kk + t];
                afr[m][1] = Qs[(rb + g + 8) * 68 + kk + t];
                afr[m][2] = Qs[(rb + g) * 68 + kk + t + 4];
                afr[m][3] = Qs[(rb + g + 8) * 68 + kk + t + 4];
            }
#pragma unroll
            for (int ni = 0; ni < 8; ni++) {
                bfr[ni][0] = Kc[(ni * 8 + g) * 68 + kk + t];
                bfr[ni][1] = Kc[(ni * 8 + g) * 68 + kk + t + 4];
            }
#pragma unroll
            for (int m = 0; m < 2; m++)
#pragma unroll
                for (int ni = 0; ni < 8; ni++)
                    mma_tf32(sacc[m][ni], afr[m], bfr[ni]);
        }

        // ---- online softmax, warp-local
#pragma unroll
        for (int m = 0; m < 2; m++) {
#pragma unroll
            for (int i = 0; i < 2; i++) {
                int idx = 2 * i;
                float rm = -1e30f;
#pragma unroll
                for (int ni = 0; ni < 8; ni++)
                    rm = fmaxf(rm, fmaxf(sacc[m][ni][idx], sacc[m][ni][idx + 1]));
                rm = fmaxf(rm, __shfl_xor_sync(0xffffffffu, rm, 1));
                rm = fmaxf(rm, __shfl_xor_sync(0xffffffffu, rm, 2));
                float mnew = fmaxf(mi[m][i], rm);
                float corr = __expf(mi[m][i] - mnew);
                float rs = 0.f;
#pragma unroll
                for (int ni = 0; ni < 8; ni++) {
                    float p0 = __expf(sacc[m][ni][idx]     - mnew);
                    float p1 = __expf(sacc[m][ni][idx + 1] - mnew);
                    rs += p0 + p1;
                    *(uint2*)&Ps[(wq + m * 16 + g + 8 * i) * 68 + ni * 8 + 2 * t] =
                        make_uint2(f2tf32(p0), f2tf32(p1));
                }
                rs += __shfl_xor_sync(0xffffffffu, rs, 1);
                rs += __shfl_xor_sync(0xffffffffu, rs, 2);
                li[m][i] = li[m][i] * corr + rs;
                mi[m][i] = mnew;
#pragma unroll
                for (int ni = 0; ni < 8; ni++) {
                    oacc[m][ni][idx]     *= corr;
                    oacc[m][ni][idx + 1] *= corr;
                }
            }
        }
        __syncwarp();                    // Ps writes -> PV reads (warp-private)

        // ---- O += P V : warp tile 32(q) x 64(d)
#pragma unroll
        for (int kk = 0; kk < 64; kk += 8) {
            uint32_t afr[2][4], bfr[8][2];
#pragma unroll
            for (int m = 0; m < 2; m++) {
                int rb = wq + m * 16;
                afr[m][0] = Ps[(rb + g) * 68 + kk + t];
                afr[m][1] = Ps[(rb + g + 8) * 68 + kk + t];
                afr[m][2] = Ps[(rb + g) * 68 + kk + t + 4];
                afr[m][3] = Ps[(rb + g + 8) * 68 + kk + t + 4];
            }
#pragma unroll
            for (int ni = 0; ni < 8; ni++) {
                bfr[ni][0] = Vc[(kk + t) * 72 + ni * 8 + g];
                bfr[ni][1] = Vc[(kk + t + 4) * 72 + ni * 8 + g];
            }
#pragma unroll
            for (int m = 0; m < 2; m++)
#pragma unroll
                for (int ni = 0; ni < 8; ni++)
                    mma_tf32(oacc[m][ni], afr[m], bfr[ni]);
        }
        __syncwarp();
    }

    // ---- epilogue: /l, round to tf32 (consumed by tf32 proj), write h
#pragma unroll
    for (int m = 0; m < 2; m++) {
#pragma unroll
        for (int i = 0; i < 2; i++) {
            int idx = 2 * i;
            float invl = 1.0f / li[m][i];
            int n = q0 + wq + m * 16 + g + 8 * i;
#pragma unroll
            for (int ni = 0; ni < 8; ni++) {
                int col = ni * 8 + 2 * t;
                float2 vo;
                vo.x = rnd32(oacc[m][ni][idx]     * invl);
                vo.y = rnd32(oacc[m][ni][idx + 1] * invl);
                *(float2*)&g_h[(b * NTOK + n) * DIM + hh * HD + col] = vo;
            }
        }
    }
}

// ===========================================================================
// Kernel 3: gating -> scalar g per token (fp32, one warp per token).
// ===========================================================================
__global__ __launch_bounds__(256) void gate_kernel(
    const float* __restrict__ Wr, const float* __restrict__ br,
    const float* __restrict__ Ws, const float* __restrict__ bs)
{
    const int warp = threadIdx.x >> 5, lane = threadIdx.x & 31;
    const int tok = blockIdx.x * 8 + warp;
    const float* hrow = g_h + tok * DIM;

    float hv[32];
#pragma unroll
    for (int kk = 0; kk < 32; kk++) hv[kk] = hrow[lane + 32 * kk];

    float myLogit = -1e30f;
#pragma unroll
    for (int wi = 0; wi < 17; wi++) {
        const float* wrow = (wi < 15) ? (Wr + wi * DIM) : (Ws + (wi - 15) * DIM);
        float sum = 0.f;
#pragma unroll
        for (int kk = 0; kk < 32; kk++) sum += hv[kk] * wrow[lane + 32 * kk];
#pragma unroll
        for (int off = 16; off; off >>= 1) sum += __shfl_xor_sync(0xffffffffu, sum, off);
        float bias = (wi < 15) ? br[wi] : bs[wi - 15];
        if (lane == wi) myLogit = sum + bias;
    }

    float v15 = (lane < 15) ? myLogit : -1e30f;
    float m15 = v15;
#pragma unroll
    for (int off = 16; off; off >>= 1) m15 = fmaxf(m15, __shfl_xor_sync(0xffffffffu, m15, off));
    float e = (lane < 15) ? __expf(myLogit - m15) : 0.f;
    float ssum = e;
#pragma unroll
    for (int off = 16; off; off >>= 1) ssum += __shfl_xor_sync(0xffffffffu, ssum, off);
    float inv = 1.f / ssum;

    float vv = e;
    float gsum3 = 0.f;
    for (int pick = 0; pick < 3; pick++) {
        float pm = vv;
#pragma unroll
        for (int off = 16; off; off >>= 1) pm = fmaxf(pm, __shfl_xor_sync(0xffffffffu, pm, off));
        gsum3 += pm;
        unsigned eqm = __ballot_sync(0xffffffffu, vv == pm);
        int first = __ffs(eqm) - 1;
        if (lane == first) vv = -1.f;
    }
    gsum3 *= inv;

    float l15 = __shfl_sync(0xffffffffu, myLogit, 15);
    float l16 = __shfl_sync(0xffffffffu, myLogit, 16);
    float m2 = fmaxf(l15, l16);
    float e0 = __expf(l15 - m2), e1 = __expf(l16 - m2);
    float s2 = e0 + e1;
    float s0 = e0 / s2, s1 = e1 / s2;

    if (lane == 0)
        g_gate[tok] = 2.f * s0 * (s0 + s1) + 6.f * s1 * gsum3;
}

// ===========================================================================
// Kernel 4: output projection (tf32, cp.async, cvt-free mainloop).
// out = g .* (h @ Wp^T) + bp.  grid = (32, 8), 256 threads.
// ===========================================================================
__global__ __launch_bounds__(256, 2) void proj_gemm(
    const float* __restrict__ bp, float* __restrict__ out)
{
    __shared__ uint32_t As[2][128][20];
    __shared__ uint32_t Bs[2][128][20];

    const int tid  = threadIdx.x;
    const int warp = tid >> 5, lane = tid & 31;
    const int g = lane >> 2, t = lane & 3;
    const int wm = (warp >> 2) * 64;
    const int wn = (warp & 3) * 32;

    const int m0 = blockIdx.x * 128;
    const int n0 = blockIdx.y * 128;
    const int row = tid >> 1;
    const int q8  = (tid & 1) * 8;

    float acc[4][4][4];
#pragma unroll
    for (int i = 0; i < 4; i++)
#pragma unroll
        for (int j = 0; j < 4; j++)
#pragma unroll
            for (int r = 0; r < 4; r++) acc[i][j][r] = 0.f;

    const float* aPtr = g_h + (m0 + row) * DIM + q8;
    const float* bPtr = g_wp + (n0 + row) * DIM + q8;
    const uint32_t sA0 = (uint32_t)__cvta_generic_to_shared(&As[0][row][q8]);
    const uint32_t sB0 = (uint32_t)__cvta_generic_to_shared(&Bs[0][row][q8]);
    const uint32_t stageBytes = 128 * 20 * 4;

    cp_async16(sA0,      aPtr);
    cp_async16(sA0 + 16, aPtr + 4);
    cp_async16(sB0,      bPtr);
    cp_async16(sB0 + 16, bPtr + 4);
    cp_commit();

    for (int kt = 0; kt < 64; kt++) {
        const int cur = kt & 1;
        cp_wait0();
        __syncthreads();
        if (kt < 63) {
            const uint32_t off = (cur ^ 1) * stageBytes;
            const float* ap = aPtr + (kt + 1) * 16;
            const float* bp2 = bPtr + (kt + 1) * 16;
            cp_async16(sA0 + off,      ap);
            cp_async16(sA0 + off + 16, ap + 4);
            cp_async16(sB0 + off,      bp2);
            cp_async16(sB0 + off + 16, bp2 + 4);
            cp_commit();
        }

#pragma unroll
        for (int kk = 0; kk < 16; kk += 8) {
            uint32_t afr[4][4], bfr[4][2];
#pragma unroll
            for (int mi = 0; mi < 4; mi++) {
                int rb = wm + mi * 16;
                afr[mi][0] = As[cur][rb + g][kk + t];
                afr[mi][1] = As[cur][rb + g + 8][kk + t];
                afr[mi][2] = As[cur][rb + g][kk + t + 4];
                afr[mi][3] = As[cur][rb + g + 8][kk + t + 4];
            }
#pragma unroll
            for (int ni = 0; ni < 4; ni++) {
                int nb = wn + ni * 8;
                bfr[ni][0] = Bs[cur][nb + g][kk + t];
                bfr[ni][1] = Bs[cur][nb + g][kk + t + 4];
            }
#pragma unroll
            for (int mi = 0; mi < 4; mi++)
#pragma unroll
                for (int ni = 0; ni < 4; ni++)
                    mma_tf32(acc[mi][ni], afr[mi], bfr[ni]);
        }
    }

    // epilogue: apply row gate, add bias
#pragma unroll
    for (int mi = 0; mi < 4; mi++) {
#pragma unroll
        for (int h = 0; h < 2; h++) {
            int m = m0 + wm + mi * 16 + g + 8 * h;
            float gm = g_gate[m];
#pragma unroll
            for (int ni = 0; ni < 4; ni++) {
                int col = n0 + wn + ni * 8 + 2 * t;
                float2 vo;
                vo.x = gm * acc[mi][ni][2 * h + 0] + bp[col + 0];
                vo.y = gm * acc[mi][ni][2 * h + 1] + bp[col + 1];
                *(float2*)&out[m * DIM + col] = vo;
            }
        }
    }
}

// ===========================================================================
extern "C" void kernel_launch(void* const* d_in, const int* in_sizes, int n_in,
                              void* d_out, int out_size)
{
    const float* x  = (const float*)d_in[0];
    const float* Wq = (const float*)d_in[1];
    const float* bq = (const float*)d_in[2];
    const float* Wk = (const float*)d_in[3];
    const float* bk = (const float*)d_in[4];
    const float* Wv = (const float*)d_in[5];
    const float* bv = (const float*)d_in[6];
    const float* Wp = (const float*)d_in[7];
    const float* bp = (const float*)d_in[8];
    const float* Wr = (const float*)d_in[9];
    const float* br = (const float*)d_in[10];
    const float* Ws = (const float*)d_in[11];
    const float* bs = (const float*)d_in[12];
    const float* tp = (const float*)d_in[13];
    const float* qe = (const float*)d_in[14];
    float* out = (float*)d_out;

    cudaFuncSetAttribute(attn_kernel,
                         cudaFuncAttributeMaxDynamicSharedMemorySize, ATTN_SMEM);

    float *dx, *dwq, *dwk, *dwv, *dwp;
    cudaGetSymbolAddress((void**)&dx,  g_x);
    cudaGetSymbolAddress((void**)&dwq, g_wq);
    cudaGetSymbolAddress((void**)&dwk, g_wk);
    cudaGetSymbolAddress((void**)&dwv, g_wv);
    cudaGetSymbolAddress((void**)&dwp, g_wp);

    cvt_kernel<<<512, 256>>>((const float4*)x,  (float4*)dx,  M_TOT * DIM / 4);
    cvt_kernel<<<256, 256>>>((const float4*)Wq, (float4*)dwq, DIM * DIM / 4);
    cvt_kernel<<<256, 256>>>((const float4*)Wk, (float4*)dwk, DIM * DIM / 4);
    cvt_kernel<<<256, 256>>>((const float4*)Wv, (float4*)dwv, DIM * DIM / 4);
    cvt_kernel<<<256, 256>>>((const float4*)Wp, (float4*)dwp, DIM * DIM / 4);

    qkv_gemm<<<dim3(32, 24), 256>>>(bq, bk, bv);
    attn_kernel<<<dim3(8, 32), 256, ATTN_SMEM>>>(tp, qe);
    gate_kernel<<<512, 256>>>(Wr, br, Ws, bs);
    proj_gemm<<<dim3(32, 8), 256>>>(bp, out);
}

// round 14
// speedup vs baseline: 3.3124x; 1.0768x over previous
#include <cuda_runtime.h>
#include <math.h>
#include <stdint.h>

#define B_SZ   2
#define NTOK   2048
#define DIM    1024
#define NH     16
#define HD     64
#define M_TOT  (B_SZ * NTOK)      // 4096
#define QT     256                // attention query tile

// ---------------- scratch (device globals; no runtime allocation) ----------
__device__ float g_x [M_TOT * DIM];            // tf32-rounded x
__device__ float g_wq[DIM * DIM];              // tf32-rounded weights
__device__ float g_wk[DIM * DIM];
__device__ float g_wv[DIM * DIM];
__device__ float g_wp[DIM * DIM];
__device__ float g_q[B_SZ * NH * NTOK * HD];   // [B,H,N,hd] (tf32-rounded)
__device__ float g_k[B_SZ * NH * NTOK * HD];
__device__ float g_v[B_SZ * NH * NTOK * HD];
__device__ float g_h[M_TOT * DIM];             // attention out (tf32-rounded)
__device__ float g_gate[M_TOT];                // per-token gate scalar

// ---------------- tf32 helpers --------------------------------------------
__device__ __forceinline__ uint32_t f2tf32(float x) {
    uint32_t r;
    asm("cvt.rna.tf32.f32 %0, %1;" : "=r"(r) : "f"(x));
    return r;
}
__device__ __forceinline__ float rnd32(float x) { return __uint_as_float(f2tf32(x)); }

// D(16x8) += A(16x8,row) * B(8x8,col);  tf32 in, f32 accum
// A regs: a0=(g,t) a1=(g+8,t) a2=(g,t+4) a3=(g+8,t+4)
// B regs: b0=(k=t,n=g) b1=(k=t+4,n=g)
// C regs: c0=(g,2t) c1=(g,2t+1) c2=(g+8,2t) c3=(g+8,2t+1)
__device__ __forceinline__ void mma_tf32(float* c, const uint32_t* a, const uint32_t* b) {
    asm volatile(
        "mma.sync.aligned.m16n8k8.row.col.f32.tf32.tf32.f32 "
        "{%0,%1,%2,%3}, {%4,%5,%6,%7}, {%8,%9}, {%0,%1,%2,%3};"
        : "+f"(c[0]), "+f"(c[1]), "+f"(c[2]), "+f"(c[3])
        : "r"(a[0]), "r"(a[1]), "r"(a[2]), "r"(a[3]), "r"(b[0]), "r"(b[1]));
}

// One ldmatrix.x4: four 8x8 b16 tiles == one 16x8-tf32 A-frag or two B-frags.
#define LDSM4(r0, r1, r2, r3, addr) \
    asm volatile("ldmatrix.sync.aligned.m8n8.x4.shared.b16 {%0,%1,%2,%3}, [%4];" \
        : "=r"(r0), "=r"(r1), "=r"(r2), "=r"(r3) : "r"(addr))

__device__ __forceinline__ void cp_async16(uint32_t smem_addr, const void* gptr) {
    asm volatile("cp.async.cg.shared.global [%0], [%1], 16;"
                 :: "r"(smem_addr), "l"(gptr));
}
__device__ __forceinline__ void cp_commit() {
    asm volatile("cp.async.commit_group;");
}
__device__ __forceinline__ void cp_wait0() {
    asm volatile("cp.async.wait_group 0;");
}

// ===========================================================================
// Kernel 0: pre-convert fp32 -> tf32-rounded fp32 (grid-stride float4).
// ===========================================================================
__global__ void cvt_kernel(const float4* __restrict__ src, float4* __restrict__ dst, int n4)
{
    int i = blockIdx.x * blockDim.x + threadIdx.x;
    int stride = gridDim.x * blockDim.x;
    for (; i < n4; i += stride) {
        float4 v = src[i];
        dst[i] = make_float4(rnd32(v.x), rnd32(v.y), rnd32(v.z), rnd32(v.w));
    }
}

// ===========================================================================
// Kernel 1: fused QKV projection (tf32, cp.async 2-stage, ldmatrix frags).
// Block 128x128, 8 warps (64x32).  grid = (32, 24), 256 threads.
// ===========================================================================
__global__ __launch_bounds__(256, 2) void qkv_gemm(
    const float* __restrict__ bq, const float* __restrict__ bk,
    const float* __restrict__ bv)
{
    __shared__ __align__(16) uint32_t As[2][128][20];
    __shared__ __align__(16) uint32_t Bs[2][128][20];

    const int tid  = threadIdx.x;
    const int warp = tid >> 5, lane = tid & 31;
    const int g = lane >> 2, t = lane & 3;
    const int wm = (warp >> 2) * 64;
    const int wn = (warp & 3) * 32;

    // ldmatrix per-lane address components
    const int quad = lane >> 3, r8 = lane & 7;
    const int aRow = ((quad & 1) << 3) + r8;   // +8 rows for quads 1,3
    const int aCol = (quad >> 1) << 2;         // +4 words for quads 2,3
    const int bRow = ((quad >> 1) << 3) + r8;  // +8 rows for quads 2,3
    const int bCol = (quad & 1) << 2;          // +4 words for quads 1,3

    const int m0 = blockIdx.x * 128;
    const int n0 = blockIdx.y * 128;
    const int seg = n0 >> 10;
    const float* W    = (seg == 0) ? g_wq : (seg == 1) ? g_wk : g_wv;
    const float* bias = (seg == 0) ? bq : (seg == 1) ? bk : bv;
    float* outp       = (seg == 0) ? g_q : (seg == 1) ? g_k : g_v;
    const int ncol0 = n0 & 1023;

    const int row = tid >> 1;
    const int q8  = (tid & 1) * 8;

    float acc[4][4][4];
#pragma unroll
    for (int i = 0; i < 4; i++)
#pragma unroll
        for (int j = 0; j < 4; j++)
#pragma unroll
            for (int r = 0; r < 4; r++) acc[i][j][r] = 0.f;

    const float* aPtr = g_x + (m0 + row) * DIM + q8;
    const float* bPtr = W + (ncol0 + row) * DIM + q8;
    const uint32_t sA0 = (uint32_t)__cvta_generic_to_shared(&As[0][row][q8]);
    const uint32_t sB0 = (uint32_t)__cvta_generic_to_shared(&Bs[0][row][q8]);
    const uint32_t sAb = (uint32_t)__cvta_generic_to_shared(&As[0][0][0]);
    const uint32_t sBb = (uint32_t)__cvta_generic_to_shared(&Bs[0][0][0]);
    const uint32_t stageBytes = 128 * 20 * 4;

    cp_async16(sA0,      aPtr);
    cp_async16(sA0 + 16, aPtr + 4);
    cp_async16(sB0,      bPtr);
    cp_async16(sB0 + 16, bPtr + 4);
    cp_commit();

    for (int kt = 0; kt < 64; kt++) {
        const int cur = kt & 1;
        cp_wait0();
        __syncthreads();
        if (kt < 63) {
            const uint32_t off = (cur ^ 1) * stageBytes;
            const float* ap = aPtr + (kt + 1) * 16;
            const float* bp = bPtr + (kt + 1) * 16;
            cp_async16(sA0 + off,      ap);
            cp_async16(sA0 + off + 16, ap + 4);
            cp_async16(sB0 + off,      bp);
            cp_async16(sB0 + off + 16, bp + 4);
            cp_commit();
        }

        const uint32_t sAc = sAb + cur * stageBytes;
        const uint32_t sBc = sBb + cur * stageBytes;
#pragma unroll
        for (int kk = 0; kk < 16; kk += 8) {
            uint32_t afr[4][4], bfr[4][2];
#pragma unroll
            for (int mi = 0; mi < 4; mi++)
                LDSM4(afr[mi][0], afr[mi][1], afr[mi][2], afr[mi][3],
                      sAc + (((wm + mi * 16 + aRow) * 20) + kk + aCol) * 4);
#pragma unroll
            for (int n2 = 0; n2 < 2; n2++)
                LDSM4(bfr[2 * n2][0], bfr[2 * n2][1], bfr[2 * n2 + 1][0], bfr[2 * n2 + 1][1],
                      sBc + (((wn + n2 * 16 + bRow) * 20) + kk + bCol) * 4);
#pragma unroll
            for (int mi = 0; mi < 4; mi++)
#pragma unroll
                for (int ni = 0; ni < 4; ni++)
                    mma_tf32(acc[mi][ni], afr[mi], bfr[ni]);
        }
    }

    // epilogue: bias, round to tf32 (consumed by tf32 attention), scatter
#pragma unroll
    for (int mi = 0; mi < 4; mi++) {
#pragma unroll
        for (int h = 0; h < 2; h++) {
            int m = m0 + wm + mi * 16 + g + 8 * h;
            int bb = m >> 11, n = m & 2047;
#pragma unroll
            for (int ni = 0; ni < 4; ni++) {
                int col = ncol0 + wn + ni * 8 + 2 * t;
                int head = col >> 6, d = col & 63;
                float2 vo;
                vo.x = rnd32(acc[mi][ni][2 * h + 0] + bias[col + 0]);
                vo.y = rnd32(acc[mi][ni][2 * h + 1] + bias[col + 1]);
                *(float2*)&outp[(((bb * NH + head) * NTOK) + n) * HD + d] = vo;
            }
        }
    }
}

// ===========================================================================
// Kernel 2: flash attention, tf32 mma, cp.async K/V double buffer,
// ldmatrix fragment loads for Q, K, P (V stays scalar: k-major layout).
// grid = (8, 32), 256 threads, ~206KB dynamic smem.
// ===========================================================================
#define ATTN_SMEM ((QT * 68 * 2 + 2 * 64 * 68 + 2 * 64 * 72) * 4)

__global__ __launch_bounds__(256, 1) void attn_kernel(
    const float* __restrict__ temperature,
    const float* __restrict__ qe)
{
    extern __shared__ uint32_t smu[];
    uint32_t* Qs = smu;                       // [q][d]   stride 68, QT rows
    uint32_t* Ks = Qs + QT * 68;              // [2][key][d] stride 68
    uint32_t* Vs = Ks + 2 * 64 * 68;          // [2][key][d] stride 72
    uint32_t* Ps = Vs + 2 * 64 * 72;          // [q][key] stride 68, QT rows

    const int tid  = threadIdx.x;
    const int warp = tid >> 5, lane = tid & 31;
    const int g = lane >> 2, t = lane & 3;
    const int wq = warp * 32;

    const int quad = lane >> 3, r8 = lane & 7;
    const int aRow = ((quad & 1) << 3) + r8;
    const int aCol = (quad >> 1) << 2;
    const int bRow = ((quad >> 1) << 3) + r8;
    const int bCol = (quad & 1) << 2;

    const int bh = blockIdx.y;
    const int b = bh >> 4, hh = bh & 15;
    const int q0 = blockIdx.x * QT;

    const float* qbase = g_q + (bh * NTOK + q0) * HD;
    const float* kbase = g_k + (long)bh * NTOK * HD;
    const float* vbase = g_v + (long)bh * NTOK * HD;

    const uint32_t sQ  = (uint32_t)__cvta_generic_to_shared(Qs);
    const uint32_t sKb = (uint32_t)__cvta_generic_to_shared(Ks);
    const uint32_t sP  = (uint32_t)__cvta_generic_to_shared(Ps);

    // ---- K/V cp.async staging geometry: row j, 4 float4 per thread
    const int j  = tid >> 2;
    const int c4 = tid & 3;
    const uint32_t sK0 = (uint32_t)__cvta_generic_to_shared(&Ks[j * 68 + c4 * 16]);
    const uint32_t sV0 = (uint32_t)__cvta_generic_to_shared(&Vs[j * 72 + c4 * 16]);
    const uint32_t kStage = 64 * 68 * 4, vStage = 64 * 72 * 4;
    const float* kp0 = kbase + j * HD + c4 * 16;
    const float* vp0 = vbase + j * HD + c4 * 16;

#pragma unroll
    for (int f = 0; f < 4; f++) {
        cp_async16(sK0 + f * 16, kp0 + f * 4);
        cp_async16(sV0 + f * 16, vp0 + f * 4);
    }
    cp_commit();

    // ---- Q preprocess (overlaps the K/V load): one row per thread
    {
        int r = tid;
        float qv[64];
        float ss = 0.f;
#pragma unroll
        for (int f = 0; f < 16; f++) {
            float4 v = *(const float4*)(qbase + r * HD + f * 4);
            qv[f * 4 + 0] = v.x; qv[f * 4 + 1] = v.y;
            qv[f * 4 + 2] = v.z; qv[f * 4 + 3] = v.w;
            ss += v.x * v.x + v.y * v.y + v.z * v.z + v.w * v.w;
        }
        float inv = rsqrtf(ss);
        float tt = temperature[hh];
        float sp = (tt > 20.f) ? tt : log1pf(__expf(tt));
        float tc = sp * 0.125f;                      // /sqrt(64)
        const float* qeh = qe + hh * HD;
#pragma unroll
        for (int f = 0; f < 16; f++) {
            uint4 u;
            u.x = f2tf32((qv[f * 4 + 0] * inv + qeh[f * 4 + 0]) * tc);
            u.y = f2tf32((qv[f * 4 + 1] * inv + qeh[f * 4 + 1]) * tc);
            u.z = f2tf32((qv[f * 4 + 2] * inv + qeh[f * 4 + 2]) * tc);
            u.w = f2tf32((qv[f * 4 + 3] * inv + qeh[f * 4 + 3]) * tc);
            *(uint4*)&Qs[r * 68 + f * 4] = u;
        }
    }

    float oacc[2][8][4];
    float mi[2][2], li[2][2];
#pragma unroll
    for (int m = 0; m < 2; m++) {
#pragma unroll
        for (int i = 0; i < 8; i++)
#pragma unroll
            for (int r = 0; r < 4; r++) oacc[m][i][r] = 0.f;
        mi[m][0] = mi[m][1] = -1e30f;
        li[m][0] = li[m][1] = 0.f;
    }

    for (int kt = 0; kt < NTOK / 64; kt++) {
        const int cur = kt & 1;
        uint32_t* Vc = Vs + cur * 64 * 72;
        const uint32_t sKc = sKb + cur * kStage;

        cp_wait0();
        __syncthreads();                 // cur tile visible; prev compute done

        if (kt < NTOK / 64 - 1) {
            const uint32_t kOff = (cur ^ 1) * kStage;
            const uint32_t vOff = (cur ^ 1) * vStage;
            const float* kp = kp0 + (kt + 1) * 64 * HD;
            const float* vp = vp0 + (kt + 1) * 64 * HD;
#pragma unroll
            for (int f = 0; f < 4; f++) {
                cp_async16(sK0 + kOff + f * 16, kp + f * 4);
                cp_async16(sV0 + vOff + f * 16, vp + f * 4);
            }
            cp_commit();
        }

        // ---- S = Q K^T : warp tile 32(q) x 64(key)
        float sacc[2][8][4];
#pragma unroll
        for (int m = 0; m < 2; m++)
#pragma unroll
            for (int i = 0; i < 8; i++)
#pragma unroll
                for (int r = 0; r < 4; r++) sacc[m][i][r] = 0.f;

#pragma unroll
        for (int kk = 0; kk < 64; kk += 8) {
            uint32_t afr[2][4], bfr[8][2];
#pragma unroll
            for (int m = 0; m < 2; m++)
                LDSM4(afr[m][0], afr[m][1], afr[m][2], afr[m][3],
                      sQ + (((wq + m * 16 + aRow) * 68) + kk + aCol) * 4);
#pragma unroll
            for (int n2 = 0; n2 < 4; n2++)
                LDSM4(bfr[2 * n2][0], bfr[2 * n2][1], bfr[2 * n2 + 1][0], bfr[2 * n2 + 1][1],
                      sKc + (((n2 * 16 + bRow) * 68) + kk + bCol) * 4);
#pragma unroll
            for (int m = 0; m < 2; m++)
#pragma unroll
                for (int ni = 0; ni < 8; ni++)
                    mma_tf32(sacc[m][ni], afr[m], bfr[ni]);
        }

        // ---- online softmax, warp-local
#pragma unroll
        for (int m = 0; m < 2; m++) {
#pragma unroll
            for (int i = 0; i < 2; i++) {
                int idx = 2 * i;
                float rm = -1e30f;
#pragma unroll
                for (int ni = 0; ni < 8; ni++)
                    rm = fmaxf(rm, fmaxf(sacc[m][ni][idx], sacc[m][ni][idx + 1]));
                rm = fmaxf(rm, __shfl_xor_sync(0xffffffffu, rm, 1));
                rm = fmaxf(rm, __shfl_xor_sync(0xffffffffu, rm, 2));
                float mnew = fmaxf(mi[m][i], rm);
                float corr = __expf(mi[m][i] - mnew);
                float rs = 0.f;
#pragma unroll
                for (int ni = 0; ni < 8; ni++) {
                    float p0 = __expf(sacc[m][ni][idx]     - mnew);
                    float p1 = __expf(sacc[m][ni][idx + 1] - mnew);
                    rs += p0 + p1;
                    *(uint2*)&Ps[(wq + m * 16 + g + 8 * i) * 68 + ni * 8 + 2 * t] =
                        make_uint2(f2tf32(p0), f2tf32(p1));
                }
                rs += __shfl_xor_sync(0xffffffffu, rs, 1);
                rs += __shfl_xor_sync(0xffffffffu, rs, 2);
                li[m][i] = li[m][i] * corr + rs;
                mi[m][i] = mnew;
#pragma unroll
                for (int ni = 0; ni < 8; ni++) {
                    oacc[m][ni][idx]     *= corr;
                    oacc[m][ni][idx + 1] *= corr;
                }
            }
        }
        __syncwarp();                    // Ps writes -> ldmatrix reads (warp-private)

        // ---- O += P V : warp tile 32(q) x 64(d)
#pragma unroll
        for (int kk = 0; kk < 64; kk += 8) {
            uint32_t afr[2][4], bfr[8][2];
#pragma unroll
            for (int m = 0; m < 2; m++)
                LDSM4(afr[m][0], afr[m][1], afr[m][2], afr[m][3],
                      sP + (((wq + m * 16 + aRow) * 68) + kk + aCol) * 4);
#pragma unroll
            for (int ni = 0; ni < 8; ni++) {
                bfr[ni][0] = Vc[(kk + t) * 72 + ni * 8 + g];
                bfr[ni][1] = Vc[(kk + t + 4) * 72 + ni * 8 + g];
            }
#pragma unroll
            for (int m = 0; m < 2; m++)
#pragma unroll
                for (int ni = 0; ni < 8; ni++)
                    mma_tf32(oacc[m][ni], afr[m], bfr[ni]);
        }
        __syncwarp();
    }

    // ---- epilogue: /l, round to tf32 (consumed by tf32 proj), write h
#pragma unroll
    for (int m = 0; m < 2; m++) {
#pragma unroll
        for (int i = 0; i < 2; i++) {
            int idx = 2 * i;
            float invl = 1.0f / li[m][i];
            int n = q0 + wq + m * 16 + g + 8 * i;
#pragma unroll
            for (int ni = 0; ni < 8; ni++) {
                int col = ni * 8 + 2 * t;
                float2 vo;
                vo.x = rnd32(oacc[m][ni][idx]     * invl);
                vo.y = rnd32(oacc[m][ni][idx + 1] * invl);
                *(float2*)&g_h[(b * NTOK + n) * DIM + hh * HD + col] = vo;
            }
        }
    }
}

// ===========================================================================
// Kernel 3: gating -> scalar g per token (fp32, one warp per token).
// ===========================================================================
__global__ __launch_bounds__(256) void gate_kernel(
    const float* __restrict__ Wr, const float* __restrict__ br,
    const float* __restrict__ Ws, const float* __restrict__ bs)
{
    const int warp = threadIdx.x >> 5, lane = threadIdx.x & 31;
    const int tok = blockIdx.x * 8 + warp;
    const float* hrow = g_h + tok * DIM;

    float hv[32];
#pragma unroll
    for (int kk = 0; kk < 32; kk++) hv[kk] = hrow[lane + 32 * kk];

    float myLogit = -1e30f;
#pragma unroll
    for (int wi = 0; wi < 17; wi++) {
        const float* wrow = (wi < 15) ? (Wr + wi * DIM) : (Ws + (wi - 15) * DIM);
        float sum = 0.f;
#pragma unroll
        for (int kk = 0; kk < 32; kk++) sum += hv[kk] * wrow[lane + 32 * kk];
#pragma unroll
        for (int off = 16; off; off >>= 1) sum += __shfl_xor_sync(0xffffffffu, sum, off);
        float bias = (wi < 15) ? br[wi] : bs[wi - 15];
        if (lane == wi) myLogit = sum + bias;
    }

    float v15 = (lane < 15) ? myLogit : -1e30f;
    float m15 = v15;
#pragma unroll
    for (int off = 16; off; off >>= 1) m15 = fmaxf(m15, __shfl_xor_sync(0xffffffffu, m15, off));
    float e = (lane < 15) ? __expf(myLogit - m15) : 0.f;
    float ssum = e;
#pragma unroll
    for (int off = 16; off; off >>= 1) ssum += __shfl_xor_sync(0xffffffffu, ssum, off);
    float inv = 1.f / ssum;

    float vv = e;
    float gsum3 = 0.f;
    for (int pick = 0; pick < 3; pick++) {
        float pm = vv;
#pragma unroll
        for (int off = 16; off; off >>= 1) pm = fmaxf(pm, __shfl_xor_sync(0xffffffffu, pm, off));
        gsum3 += pm;
        unsigned eqm = __ballot_sync(0xffffffffu, vv == pm);
        int first = __ffs(eqm) - 1;
        if (lane == first) vv = -1.f;
    }
    gsum3 *= inv;

    float l15 = __shfl_sync(0xffffffffu, myLogit, 15);
    float l16 = __shfl_sync(0xffffffffu, myLogit, 16);
    float m2 = fmaxf(l15, l16);
    float e0 = __expf(l15 - m2), e1 = __expf(l16 - m2);
    float s2 = e0 + e1;
    float s0 = e0 / s2, s1 = e1 / s2;

    if (lane == 0)
        g_gate[tok] = 2.f * s0 * (s0 + s1) + 6.f * s1 * gsum3;
}

// ===========================================================================
// Kernel 4: output projection (tf32, cp.async, ldmatrix frags).
// out = g .* (h @ Wp^T) + bp.  grid = (32, 8), 256 threads.
// ===========================================================================
__global__ __launch_bounds__(256, 2) void proj_gemm(
    const float* __restrict__ bp, float* __restrict__ out)
{
    __shared__ __align__(16) uint32_t As[2][128][20];
    __shared__ __align__(16) uint32_t Bs[2][128][20];

    const int tid  = threadIdx.x;
    const int warp = tid >> 5, lane = tid & 31;
    const int g = lane >> 2, t = lane & 3;
    const int wm = (warp >> 2) * 64;
    const int wn = (warp & 3) * 32;

    const int quad = lane >> 3, r8 = lane & 7;
    const int aRow = ((quad & 1) << 3) + r8;
    const int aCol = (quad >> 1) << 2;
    const int bRow = ((quad >> 1) << 3) + r8;
    const int bCol = (quad & 1) << 2;

    const int m0 = blockIdx.x * 128;
    const int n0 = blockIdx.y * 128;
    const int row = tid >> 1;
    const int q8  = (tid & 1) * 8;

    float acc[4][4][4];
#pragma unroll
    for (int i = 0; i < 4; i++)
#pragma unroll
        for (int j = 0; j < 4; j++)
#pragma unroll
            for (int r = 0; r < 4; r++) acc[i][j][r] = 0.f;

    const float* aPtr = g_h + (m0 + row) * DIM + q8;
    const float* bPtr = g_wp + (n0 + row) * DIM + q8;
    const uint32_t sA0 = (uint32_t)__cvta_generic_to_shared(&As[0][row][q8]);
    const uint32_t sB0 = (uint32_t)__cvta_generic_to_shared(&Bs[0][row][q8]);
    const uint32_t sAb = (uint32_t)__cvta_generic_to_shared(&As[0][0][0]);
    const uint32_t sBb = (uint32_t)__cvta_generic_to_shared(&Bs[0][0][0]);
    const uint32_t stageBytes = 128 * 20 * 4;

    cp_async16(sA0,      aPtr);
    cp_async16(sA0 + 16, aPtr + 4);
    cp_async16(sB0,      bPtr);
    cp_async16(sB0 + 16, bPtr + 4);
    cp_commit();

    for (int kt = 0; kt < 64; kt++) {
        const int cur = kt & 1;
        cp_wait0();
        __syncthreads();
        if (kt < 63) {
            const uint32_t off = (cur ^ 1) * stageBytes;
            const float* ap = aPtr + (kt + 1) * 16;
            const float* bp2 = bPtr + (kt + 1) * 16;
            cp_async16(sA0 + off,      ap);
            cp_async16(sA0 + off + 16, ap + 4);
            cp_async16(sB0 + off,      bp2);
            cp_async16(sB0 + off + 16, bp2 + 4);
            cp_commit();
        }

        const uint32_t sAc = sAb + cur * stageBytes;
        const uint32_t sBc = sBb + cur * stageBytes;
#pragma unroll
        for (int kk = 0; kk < 16; kk += 8) {
            uint32_t afr[4][4], bfr[4][2];
#pragma unroll
            for (int mi = 0; mi < 4; mi++)
                LDSM4(afr[mi][0], afr[mi][1], afr[mi][2], afr[mi][3],
                      sAc + (((wm + mi * 16 + aRow) * 20) + kk + aCol) * 4);
#pragma unroll
            for (int n2 = 0; n2 < 2; n2++)
                LDSM4(bfr[2 * n2][0], bfr[2 * n2][1], bfr[2 * n2 + 1][0], bfr[2 * n2 + 1][1],
                      sBc + (((wn + n2 * 16 + bRow) * 20) + kk + bCol) * 4);
#pragma unroll
            for (int mi = 0; mi < 4; mi++)
#pragma unroll
                for (int ni = 0; ni < 4; ni++)
                    mma_tf32(acc[mi][ni], afr[mi], bfr[ni]);
        }
    }

    // epilogue: apply row gate, add bias
#pragma unroll
    for (int mi = 0; mi < 4; mi++) {
#pragma unroll
        for (int h = 0; h < 2; h++) {
            int m = m0 + wm + mi * 16 + g + 8 * h;
            float gm = g_gate[m];
#pragma unroll
            for (int ni = 0; ni < 4; ni++) {
                int col = n0 + wn + ni * 8 + 2 * t;
                float2 vo;
                vo.x = gm * acc[mi][ni][2 * h + 0] + bp[col + 0];
                vo.y = gm * acc[mi][ni][2 * h + 1] + bp[col + 1];
                *(float2*)&out[m * DIM + col] = vo;
            }
        }
    }
}

// ===========================================================================
extern "C" void kernel_launch(void* const* d_in, const int* in_sizes, int n_in,
                              void* d_out, int out_size)
{
    const float* x  = (const float*)d_in[0];
    const float* Wq = (const float*)d_in[1];
    const float* bq = (const float*)d_in[2];
    const float* Wk = (const float*)d_in[3];
    const float* bk = (const float*)d_in[4];
    const float* Wv = (const float*)d_in[5];
    const float* bv = (const float*)d_in[6];
    const float* Wp = (const float*)d_in[7];
    const float* bp = (const float*)d_in[8];
    const float* Wr = (const float*)d_in[9];
    const float* br = (const float*)d_in[10];
    const float* Ws = (const float*)d_in[11];
    const float* bs = (const float*)d_in[12];
    const float* tp = (const float*)d_in[13];
    const float* qe = (const float*)d_in[14];
    float* out = (float*)d_out;

    cudaFuncSetAttribute(attn_kernel,
                         cudaFuncAttributeMaxDynamicSharedMemorySize, ATTN_SMEM);

    float *dx, *dwq, *dwk, *dwv, *dwp;
    cudaGetSymbolAddress((void**)&dx,  g_x);
    cudaGetSymbolAddress((void**)&dwq, g_wq);
    cudaGetSymbolAddress((void**)&dwk, g_wk);
    cudaGetSymbolAddress((void**)&dwv, g_wv);
    cudaGetSymbolAddress((void**)&dwp, g_wp);

    cvt_kernel<<<512, 256>>>((const float4*)x,  (float4*)dx,  M_TOT * DIM / 4);
    cvt_kernel<<<256, 256>>>((const float4*)Wq, (float4*)dwq, DIM * DIM / 4);
    cvt_kernel<<<256, 256>>>((const float4*)Wk, (float4*)dwk, DIM * DIM / 4);
    cvt_kernel<<<256, 256>>>((const float4*)Wv, (float4*)dwv, DIM * DIM / 4);
    cvt_kernel<<<256, 256>>>((const float4*)Wp, (float4*)dwp, DIM * DIM / 4);

    qkv_gemm<<<dim3(32, 24), 256>>>(bq, bk, bv);
    attn_kernel<<<dim3(8, 32), 256, ATTN_SMEM>>>(tp, qe);
    gate_kernel<<<512, 256>>>(Wr, br, Ws, bs);
    proj_gemm<<<dim3(32, 8), 256>>>(bp, out);
}